// round 3
// baseline (speedup 1.0000x reference)
#include <cuda_runtime.h>
#include <cstdint>
#include <math.h>

#define S_LEN 256
#define HID   1024
#define BATCH 128
#define NGATE 4096   // 4 * HID, gate-interleaved: n = j0*4 + gate (f,i,g,o)
#define KDIM  1024

typedef unsigned long long u64;

// ---------------- device scratch (no allocs allowed) ----------------
__device__ float g_Wx[(size_t)NGATE * KDIM];      // 16 MB  x-part weights, [n][k]
__device__ float g_Wh[(size_t)NGATE * KDIM];      // 16 MB  h-part weights, [n][k]
__device__ float g_bias[NGATE];
__device__ float g_Gx[(size_t)BATCH * S_LEN * NGATE];  // 512 MB: bias + x@Wx^T, row m=b*S+t
__device__ float g_hbuf[2][BATCH * HID];          // ping-pong h state
__device__ float g_c[BATCH * HID];                // c state

// ---------------- f32x2 packed-FMA helpers ----------------
__device__ __forceinline__ u64 pack2(float lo, float hi) {
    u64 v; asm("mov.b64 %0, {%1, %2};" : "=l"(v) : "f"(lo), "f"(hi)); return v;
}
__device__ __forceinline__ float2 unpack2(u64 v) {
    unsigned lo, hi;
    asm("mov.b64 {%0, %1}, %2;" : "=r"(lo), "=r"(hi) : "l"(v));
    return make_float2(__uint_as_float(lo), __uint_as_float(hi));
}
__device__ __forceinline__ u64 ffma2(u64 a, u64 b, u64 c) {
    u64 d; asm("fma.rn.f32x2 %0, %1, %2, %3;" : "=l"(d) : "l"(a), "l"(b), "l"(c)); return d;
}

__device__ __forceinline__ float sigmoidf_(float x) { return 1.0f / (1.0f + expf(-x)); }

// ---------------- init: zero h0 and c0 ----------------
__global__ void init_state() {
    int i = blockIdx.x * blockDim.x + threadIdx.x;
    if (i < BATCH * HID) { g_hbuf[0][i] = 0.0f; g_c[i] = 0.0f; }
}

// ---------------- repack weights into gate-interleaved [n][k] ----------------
__global__ void repack(const float* __restrict__ Wf, const float* __restrict__ bf,
                       const float* __restrict__ Wi, const float* __restrict__ bi,
                       const float* __restrict__ Wc, const float* __restrict__ bc,
                       const float* __restrict__ Wo, const float* __restrict__ bo) {
    int idx = blockIdx.x * blockDim.x + threadIdx.x;
    if (idx >= NGATE * KDIM) return;
    int n = idx >> 10;           // n = j0*4 + gate
    int k = idx & 1023;
    int j0 = n >> 2;
    int g  = n & 3;
    const float* W = (g == 0) ? Wf : (g == 1) ? Wi : (g == 2) ? Wc : Wo;
    // Reference weight rows act on cat(h, x): cols [0,H) = h part, [H, H+I) = x part
    g_Wh[idx] = W[(size_t)j0 * 2048 + k];
    g_Wx[idx] = W[(size_t)j0 * 2048 + 1024 + k];
    if (k == 0) {
        const float* b = (g == 0) ? bf : (g == 1) ? bi : (g == 2) ? bc : bo;
        g_bias[n] = b[j0];
    }
}

// ---------------- GEMM: C[m][n] = sum_k A[m][k] * W[n][k], fused epilogues ----------------
// STEP=false: A = x [M=32768][1024], W = g_Wx, writes g_Gx (+bias)
// STEP=true : A = g_hbuf[t&1] [128][1024], W = g_Wh, full LSTM cell epilogue
template<int BM, int BN, int BK, int TM, int TN, bool STEP>
__global__ __launch_bounds__(256) void gemm_k(const float* __restrict__ Ain,
                                              float* __restrict__ yout,
                                              int t) {
    constexpr int TX = BN / TN;          // threads along n
    const int tid = threadIdx.x;
    const int tn  = tid % TX;
    const int tm  = tid / TX;
    const int n0  = blockIdx.x * BN;
    const int m0  = blockIdx.y * BM;

    const float* A = STEP ? (const float*)g_hbuf[t & 1] : Ain;
    const float* W = STEP ? (const float*)g_Wh : (const float*)g_Wx;

    __shared__ float As[BK][BM + 4];
    __shared__ float Bs[BK][BN + 4];

    u64 acc[TM][TN / 2];
#pragma unroll
    for (int i = 0; i < TM; ++i)
#pragma unroll
        for (int j = 0; j < TN / 2; ++j) acc[i][j] = 0ull;

    const float* Ab = A + (size_t)m0 * KDIM;
    const float* Wb = W + (size_t)n0 * KDIM;

    for (int k0 = 0; k0 < KDIM; k0 += BK) {
        // stage A tile (transposed into smem)
#pragma unroll
        for (int it = 0; it < (BM * BK / 4) / 256; ++it) {
            int id  = tid + it * 256;
            int row = id >> 2;             // BK/4 = 4 float4 per row
            int kq  = (id & 3) * 4;
            const float4 v = *reinterpret_cast<const float4*>(Ab + (size_t)row * KDIM + k0 + kq);
            As[kq + 0][row] = v.x; As[kq + 1][row] = v.y;
            As[kq + 2][row] = v.z; As[kq + 3][row] = v.w;
        }
        // stage W tile
#pragma unroll
        for (int it = 0; it < (BN * BK / 4) / 256; ++it) {
            int id  = tid + it * 256;
            int row = id >> 2;
            int kq  = (id & 3) * 4;
            const float4 v = *reinterpret_cast<const float4*>(Wb + (size_t)row * KDIM + k0 + kq);
            Bs[kq + 0][row] = v.x; Bs[kq + 1][row] = v.y;
            Bs[kq + 2][row] = v.z; Bs[kq + 3][row] = v.w;
        }
        __syncthreads();

#pragma unroll
        for (int kk = 0; kk < BK; ++kk) {
            float a[TM];
#pragma unroll
            for (int i = 0; i < TM / 4; ++i) {
                float4 v = *reinterpret_cast<const float4*>(&As[kk][tm * TM + i * 4]);
                a[i * 4 + 0] = v.x; a[i * 4 + 1] = v.y;
                a[i * 4 + 2] = v.z; a[i * 4 + 3] = v.w;
            }
            u64 bv[TN / 2];
#pragma unroll
            for (int j = 0; j < TN / 4; ++j) {
                const u64* p = reinterpret_cast<const u64*>(&Bs[kk][tn * TN + j * 4]);
                bv[j * 2 + 0] = p[0];
                bv[j * 2 + 1] = p[1];
            }
#pragma unroll
            for (int i = 0; i < TM; ++i) {
                u64 a2 = pack2(a[i], a[i]);
#pragma unroll
                for (int j = 0; j < TN / 2; ++j) acc[i][j] = ffma2(a2, bv[j], acc[i][j]);
            }
        }
        __syncthreads();
    }

    if constexpr (!STEP) {
        // epilogue: add bias, store Gx
#pragma unroll
        for (int i = 0; i < TM; ++i) {
            const int m = m0 + tm * TM + i;
            const int n = n0 + tn * TN;
            float* cp = g_Gx + (size_t)m * NGATE + n;
#pragma unroll
            for (int j = 0; j < TN / 4; ++j) {
                float4 bvv = *reinterpret_cast<const float4*>(g_bias + n + j * 4);
                float2 p0 = unpack2(acc[i][j * 2 + 0]);
                float2 p1 = unpack2(acc[i][j * 2 + 1]);
                float4 o;
                o.x = p0.x + bvv.x; o.y = p0.y + bvv.y;
                o.z = p1.x + bvv.z; o.w = p1.y + bvv.w;
                *reinterpret_cast<float4*>(cp + j * 4) = o;
            }
        }
    } else {
        // TN == 4: this thread holds f,i,g,o pre-activations for hidden unit j0
        static_assert(!STEP || TN == 4, "step epilogue needs TN==4");
        const int n  = n0 + tn * TN;
        const int j0 = n >> 2;
        float* hout = g_hbuf[(t + 1) & 1];
#pragma unroll
        for (int i = 0; i < TM; ++i) {
            const int b = m0 + tm * TM + i;
            const float4 gx = *reinterpret_cast<const float4*>(
                g_Gx + ((size_t)b * S_LEN + t) * NGATE + n);
            float2 p0 = unpack2(acc[i][0]);
            float2 p1 = unpack2(acc[i][1]);
            float fpre = p0.x + gx.x;
            float ipre = p0.y + gx.y;
            float gpre = p1.x + gx.z;
            float opre = p1.y + gx.w;
            float fg = sigmoidf_(fpre);
            float ig = sigmoidf_(ipre);
            float gg = tanhf(gpre);
            float og = sigmoidf_(opre);
            const int ci = b * HID + j0;
            float cn = g_c[ci] * fg + ig * gg;
            g_c[ci] = cn;
            float hn = tanhf(cn) * og;
            hout[ci] = hn;
            yout[((size_t)b * S_LEN + t) * HID + j0] = hn;
        }
    }
}

// ---------------- launch ----------------
extern "C" void kernel_launch(void* const* d_in, const int* in_sizes, int n_in,
                              void* d_out, int out_size) {
    const float* x  = (const float*)d_in[0];
    const float* Wf = (const float*)d_in[1]; const float* bf = (const float*)d_in[2];
    const float* Wi = (const float*)d_in[3]; const float* bi = (const float*)d_in[4];
    const float* Wc = (const float*)d_in[5]; const float* bc = (const float*)d_in[6];
    const float* Wo = (const float*)d_in[7]; const float* bo = (const float*)d_in[8];
    float* out = (float*)d_out;

    init_state<<<(BATCH * HID + 255) / 256, 256>>>();
    repack<<<(NGATE * KDIM + 255) / 256, 256>>>(Wf, bf, Wi, bi, Wc, bc, Wo, bo);

    // Precompute Gx = bias + x @ Wx^T for all (b,t): M=32768, N=4096
    gemm_k<128, 128, 16, 8, 8, false>
        <<<dim3(NGATE / 128, (BATCH * S_LEN) / 128), 256>>>(x, nullptr, 0);

    // Sequential recurrence: one fused GEMM+cell kernel per timestep
    for (int t = 0; t < S_LEN; ++t) {
        gemm_k<64, 64, 16, 4, 4, true>
            <<<dim3(NGATE / 64, BATCH / 64), 256>>>(nullptr, out, t);
    }
}

// round 4
// speedup vs baseline: 1.1169x; 1.1169x over previous
#include <cuda_runtime.h>
#include <cstdint>
#include <math.h>

#define S_LEN 256
#define HID   1024
#define BATCH 128
#define NGATE 4096   // 4 * HID, gate-interleaved: n = j0*4 + gate (f,i,g,o)
#define KDIM  1024

#define NB 128       // persistent blocks (must all be co-resident; 1 per SM)
#define NT 512       // threads per persistent block
#define BKP 32       // K tile of the persistent step GEMM
#define HS_PITCH 36  // padded row pitch of staged h tile (conflict-free, 16B-aligned)
#define HS_SZ (BATCH * HS_PITCH)

typedef unsigned long long u64;

// ---------------- device scratch (no allocs allowed) ----------------
__device__ float g_Wx[(size_t)NGATE * KDIM];          // x-part weights, [n][k]
__device__ float g_Wh[(size_t)NGATE * KDIM];          // h-part weights, [n][k]
__device__ float g_bias[NGATE];
__device__ float g_Gx[(size_t)BATCH * S_LEN * NGATE]; // bias + x@Wx^T, row m=b*S+t
__device__ float g_hbuf[2][BATCH * HID];              // ping-pong h state
__device__ unsigned g_arrive;                         // grid-barrier arrive counter (self-resetting)
__device__ unsigned g_epoch;                          // grid-barrier epoch (monotone across replays)

// ---------------- f32x2 packed-FMA helpers ----------------
__device__ __forceinline__ u64 pack2(float lo, float hi) {
    u64 v; asm("mov.b64 %0, {%1, %2};" : "=l"(v) : "f"(lo), "f"(hi)); return v;
}
__device__ __forceinline__ float2 unpack2(u64 v) {
    unsigned lo, hi;
    asm("mov.b64 {%0, %1}, %2;" : "=r"(lo), "=r"(hi) : "l"(v));
    return make_float2(__uint_as_float(lo), __uint_as_float(hi));
}
__device__ __forceinline__ u64 ffma2(u64 a, u64 b, u64 c) {
    u64 d; asm("fma.rn.f32x2 %0, %1, %2, %3;" : "=l"(d) : "l"(a), "l"(b), "l"(c)); return d;
}
__device__ __forceinline__ float sigmoidf_(float x) { return 1.0f / (1.0f + expf(-x)); }

// ---------------- init: zero h0 ----------------
__global__ void init_state() {
    int i = blockIdx.x * blockDim.x + threadIdx.x;
    if (i < BATCH * HID) g_hbuf[0][i] = 0.0f;
}

// ---------------- repack weights into gate-interleaved [n][k] ----------------
__global__ void repack(const float* __restrict__ Wf, const float* __restrict__ bf,
                       const float* __restrict__ Wi, const float* __restrict__ bi,
                       const float* __restrict__ Wc, const float* __restrict__ bc,
                       const float* __restrict__ Wo, const float* __restrict__ bo) {
    int idx = blockIdx.x * blockDim.x + threadIdx.x;
    if (idx >= NGATE * KDIM) return;
    int n = idx >> 10;           // n = j0*4 + gate
    int k = idx & 1023;
    int j0 = n >> 2;
    int g  = n & 3;
    const float* W = (g == 0) ? Wf : (g == 1) ? Wi : (g == 2) ? Wc : Wo;
    // Reference weight rows act on cat(h, x): cols [0,H) = h part, [H, H+I) = x part
    g_Wh[idx] = W[(size_t)j0 * 2048 + k];
    g_Wx[idx] = W[(size_t)j0 * 2048 + 1024 + k];
    if (k == 0) {
        const float* b = (g == 0) ? bf : (g == 1) ? bi : (g == 2) ? bc : bo;
        g_bias[n] = b[j0];
    }
}

// ---------------- precompute GEMM: Gx[m][n] = bias[n] + sum_k x[m][k]*Wx[n][k] ----------------
template<int BM, int BN, int BK, int TM, int TN>
__global__ __launch_bounds__(256) void gemm_pre(const float* __restrict__ A) {
    constexpr int TX = BN / TN;
    const int tid = threadIdx.x;
    const int tn  = tid % TX;
    const int tm  = tid / TX;
    const int n0  = blockIdx.x * BN;
    const int m0  = blockIdx.y * BM;

    __shared__ float As[BK][BM + 4];
    __shared__ float Bs[BK][BN + 4];

    u64 acc[TM][TN / 2];
#pragma unroll
    for (int i = 0; i < TM; ++i)
#pragma unroll
        for (int j = 0; j < TN / 2; ++j) acc[i][j] = 0ull;

    const float* Ab = A + (size_t)m0 * KDIM;
    const float* Wb = g_Wx + (size_t)n0 * KDIM;

    for (int k0 = 0; k0 < KDIM; k0 += BK) {
#pragma unroll
        for (int it = 0; it < (BM * BK / 4) / 256; ++it) {
            int id  = tid + it * 256;
            int row = id >> 2;
            int kq  = (id & 3) * 4;
            const float4 v = *reinterpret_cast<const float4*>(Ab + (size_t)row * KDIM + k0 + kq);
            As[kq + 0][row] = v.x; As[kq + 1][row] = v.y;
            As[kq + 2][row] = v.z; As[kq + 3][row] = v.w;
        }
#pragma unroll
        for (int it = 0; it < (BN * BK / 4) / 256; ++it) {
            int id  = tid + it * 256;
            int row = id >> 2;
            int kq  = (id & 3) * 4;
            const float4 v = *reinterpret_cast<const float4*>(Wb + (size_t)row * KDIM + k0 + kq);
            Bs[kq + 0][row] = v.x; Bs[kq + 1][row] = v.y;
            Bs[kq + 2][row] = v.z; Bs[kq + 3][row] = v.w;
        }
        __syncthreads();

#pragma unroll
        for (int kk = 0; kk < BK; ++kk) {
            float a[TM];
#pragma unroll
            for (int i = 0; i < TM / 4; ++i) {
                float4 v = *reinterpret_cast<const float4*>(&As[kk][tm * TM + i * 4]);
                a[i * 4 + 0] = v.x; a[i * 4 + 1] = v.y;
                a[i * 4 + 2] = v.z; a[i * 4 + 3] = v.w;
            }
            u64 bv[TN / 2];
#pragma unroll
            for (int j = 0; j < TN / 4; ++j) {
                const u64* p = reinterpret_cast<const u64*>(&Bs[kk][tn * TN + j * 4]);
                bv[j * 2 + 0] = p[0];
                bv[j * 2 + 1] = p[1];
            }
#pragma unroll
            for (int i = 0; i < TM; ++i) {
                u64 a2 = pack2(a[i], a[i]);
#pragma unroll
                for (int j = 0; j < TN / 2; ++j) acc[i][j] = ffma2(a2, bv[j], acc[i][j]);
            }
        }
        __syncthreads();
    }

#pragma unroll
    for (int i = 0; i < TM; ++i) {
        const int m = m0 + tm * TM + i;
        const int n = n0 + tn * TN;
        float* cp = g_Gx + (size_t)m * NGATE + n;
#pragma unroll
        for (int j = 0; j < TN / 4; ++j) {
            float4 bvv = *reinterpret_cast<const float4*>(g_bias + n + j * 4);
            float2 p0 = unpack2(acc[i][j * 2 + 0]);
            float2 p1 = unpack2(acc[i][j * 2 + 1]);
            float4 o;
            o.x = p0.x + bvv.x; o.y = p0.y + bvv.y;
            o.z = p1.x + bvv.z; o.w = p1.y + bvv.w;
            *reinterpret_cast<float4*>(cp + j * 4) = o;
        }
    }
}

// ---------------- persistent recurrence kernel ----------------
// Block b owns gate-columns [b*32, b*32+32) for ALL batches. Wh slice lives in SMEM
// (k-major) for the whole kernel. c state lives in registers. h ping-pongs through
// global (L2) with __ldcg/__stcg (L1 is incoherent across SMs). One software grid
// barrier per timestep (all NB blocks are co-resident: 164KB smem forces 1 block/SM).
__global__ __launch_bounds__(NT, 1) void lstm_persist(float* __restrict__ yout) {
    extern __shared__ float sm[];
    float* Ws = sm;                 // [KDIM][32]  k-major weight slice (128 KB)
    float* hs = sm + 32 * KDIM;     // [2][BATCH][HS_PITCH] staged h tiles

    const int tid = threadIdx.x;
    const int tn  = tid & 7;        // 0..7  -> 4 gate cols each (one hidden unit)
    const int tm  = tid >> 3;       // 0..63 -> 2 batch rows each
    const int n0  = blockIdx.x * 32;
    const int j0  = (n0 >> 2) + tn; // hidden unit index
    const int r0  = tm * 2, r1 = r0 + 1;

    // --- load Wh slice transposed into SMEM (one-time) ---
    for (int it = 0; it < 16; ++it) {
        int id = tid + it * NT;                 // 8192 float4 = 32 rows x 256
        int j  = id >> 8;
        int kq = (id & 255) * 4;
        float4 v = *reinterpret_cast<const float4*>(&g_Wh[(size_t)(n0 + j) * KDIM + kq]);
        Ws[(kq + 0) * 32 + j] = v.x;
        Ws[(kq + 1) * 32 + j] = v.y;
        Ws[(kq + 2) * 32 + j] = v.z;
        Ws[(kq + 3) * 32 + j] = v.w;
    }
    __syncthreads();

    unsigned e0 = 0;
    if (tid == 0)
        asm volatile("ld.volatile.global.u32 %0, [%1];" : "=r"(e0) : "l"(&g_epoch));

    float c0 = 0.0f, c1 = 0.0f;     // cell state, register-resident across all steps

    for (int t = 0; t < S_LEN; ++t) {
        const float* hcur = g_hbuf[t & 1];
        float*       hnxt = g_hbuf[(t + 1) & 1];

        // prefetch Gx for the epilogue (DRAM latency hides under the K-loop)
        const float4 gx0 = *reinterpret_cast<const float4*>(
            &g_Gx[((size_t)r0 * S_LEN + t) * NGATE + n0 + tn * 4]);
        const float4 gx1 = *reinterpret_cast<const float4*>(
            &g_Gx[((size_t)r1 * S_LEN + t) * NGATE + n0 + tn * 4]);

        // prefetch first h tile (rows tm and tm+64, cols tn*4..+3 of the k-slab)
        float4 p0 = __ldcg(reinterpret_cast<const float4*>(hcur + (size_t)tm * KDIM + tn * 4));
        float4 p1 = __ldcg(reinterpret_cast<const float4*>(hcur + (size_t)(tm + 64) * KDIM + tn * 4));

        u64 acc00 = 0ull, acc01 = 0ull, acc10 = 0ull, acc11 = 0ull;
        int buf = 0;
        for (int k0 = 0; k0 < KDIM; k0 += BKP) {
            float* hb = hs + buf * HS_SZ;
            *reinterpret_cast<float4*>(&hb[tm * HS_PITCH + tn * 4])        = p0;
            *reinterpret_cast<float4*>(&hb[(tm + 64) * HS_PITCH + tn * 4]) = p1;
            __syncthreads();
            if (k0 + BKP < KDIM) {
                p0 = __ldcg(reinterpret_cast<const float4*>(
                        hcur + (size_t)tm * KDIM + k0 + BKP + tn * 4));
                p1 = __ldcg(reinterpret_cast<const float4*>(
                        hcur + (size_t)(tm + 64) * KDIM + k0 + BKP + tn * 4));
            }
            const float* wk  = Ws + k0 * 32;
            const float* ar0 = hb + r0 * HS_PITCH;
            const float* ar1 = hb + r1 * HS_PITCH;
#pragma unroll
            for (int kk = 0; kk < BKP; ++kk) {
                float4 b4 = *reinterpret_cast<const float4*>(&wk[kk * 32 + tn * 4]);
                u64 b01, b23;
                asm("mov.b64 %0, {%1,%2};" : "=l"(b01) : "f"(b4.x), "f"(b4.y));
                asm("mov.b64 %0, {%1,%2};" : "=l"(b23) : "f"(b4.z), "f"(b4.w));
                float a0 = ar0[kk];
                float a1 = ar1[kk];
                u64 aa0 = pack2(a0, a0);
                u64 aa1 = pack2(a1, a1);
                acc00 = ffma2(aa0, b01, acc00);
                acc01 = ffma2(aa0, b23, acc01);
                acc10 = ffma2(aa1, b01, acc10);
                acc11 = ffma2(aa1, b23, acc11);
            }
            buf ^= 1;
        }

        // --- LSTM cell epilogue (gates f,i,g,o are this thread's 4 columns) ---
        float2 q00 = unpack2(acc00), q01 = unpack2(acc01);
        float2 q10 = unpack2(acc10), q11 = unpack2(acc11);

        float f0 = sigmoidf_(q00.x + gx0.x);
        float i0 = sigmoidf_(q00.y + gx0.y);
        float g0 = tanhf    (q01.x + gx0.z);
        float o0 = sigmoidf_(q01.y + gx0.w);
        c0 = c0 * f0 + i0 * g0;
        float h0v = tanhf(c0) * o0;

        float f1 = sigmoidf_(q10.x + gx1.x);
        float i1 = sigmoidf_(q10.y + gx1.y);
        float g1 = tanhf    (q11.x + gx1.z);
        float o1 = sigmoidf_(q11.y + gx1.w);
        c1 = c1 * f1 + i1 * g1;
        float h1v = tanhf(c1) * o1;

        __stcg(&hnxt[r0 * HID + j0], h0v);
        __stcg(&hnxt[r1 * HID + j0], h1v);
        yout[((size_t)r0 * S_LEN + t) * HID + j0] = h0v;
        yout[((size_t)r1 * S_LEN + t) * HID + j0] = h1v;

        // --- grid barrier ---
        __threadfence();
        __syncthreads();
        if (tid == 0) {
            unsigned old = atomicAdd(&g_arrive, 1u);
            unsigned target = e0 + (unsigned)t + 1u;
            if (old == NB - 1) {
                atomicExch(&g_arrive, 0u);
                __threadfence();
                atomicAdd(&g_epoch, 1u);
            } else {
                unsigned cur;
                do {
                    asm volatile("ld.volatile.global.u32 %0, [%1];"
                                 : "=r"(cur) : "l"(&g_epoch));
                } while ((int)(cur - target) < 0);
            }
        }
        __syncthreads();
        __threadfence();  // acquire: order subsequent h loads after barrier
    }
}

// ---------------- launch ----------------
extern "C" void kernel_launch(void* const* d_in, const int* in_sizes, int n_in,
                              void* d_out, int out_size) {
    const float* x  = (const float*)d_in[0];
    const float* Wf = (const float*)d_in[1]; const float* bf = (const float*)d_in[2];
    const float* Wi = (const float*)d_in[3]; const float* bi = (const float*)d_in[4];
    const float* Wc = (const float*)d_in[5]; const float* bc = (const float*)d_in[6];
    const float* Wo = (const float*)d_in[7]; const float* bo = (const float*)d_in[8];
    float* out = (float*)d_out;

    init_state<<<(BATCH * HID + 255) / 256, 256>>>();
    repack<<<(NGATE * KDIM + 255) / 256, 256>>>(Wf, bf, Wi, bi, Wc, bc, Wo, bo);

    // Precompute Gx = bias + x @ Wx^T for all (b,t): M=32768, N=4096
    gemm_pre<128, 128, 16, 8, 8>
        <<<dim3(NGATE / 128, (BATCH * S_LEN) / 128), 256>>>(x);

    // Persistent recurrence: whole 256-step scan in one kernel
    const int smem_bytes = (32 * KDIM + 2 * HS_SZ) * (int)sizeof(float);  // 164 KB
    cudaFuncSetAttribute(lstm_persist, cudaFuncAttributeMaxDynamicSharedMemorySize, smem_bytes);
    lstm_persist<<<NB, NT, smem_bytes>>>(out);
}

// round 5
// speedup vs baseline: 1.1479x; 1.0277x over previous
#include <cuda_runtime.h>
#include <cstdint>
#include <math.h>

#define S_LEN 256
#define HID   1024
#define BATCH 128
#define NGATE 4096   // 4 * HID, gate-interleaved: n = j0*4 + gate (f,i,g,o)
#define KDIM  1024

#define NB 128       // persistent blocks (all co-resident; 1 per SM)
#define NT 512       // threads per persistent block
#define P2 260       // hs pitch in floats (mult of 4 -> 16B aligned rows)

typedef unsigned long long u64;

// ---------------- device scratch (no allocs allowed) ----------------
__device__ float g_Wx[(size_t)NGATE * KDIM];          // x-part weights, [n][k]
__device__ float g_Wh[(size_t)NGATE * KDIM];          // h-part weights, [n][k]
__device__ float g_bias[NGATE];
__device__ float g_Gx[(size_t)BATCH * S_LEN * NGATE]; // bias + x@Wx^T, row m=b*S+t
__device__ float g_hT[2][(size_t)HID * 256];          // h transposed + duplicated: [j][2b],[2b+1]
__device__ unsigned g_arrive;
__device__ unsigned g_epoch;

// ---------------- f32x2 helpers ----------------
__device__ __forceinline__ float2 unpack2(u64 v) {
    unsigned lo, hi;
    asm("mov.b64 {%0, %1}, %2;" : "=r"(lo), "=r"(hi) : "l"(v));
    return make_float2(__uint_as_float(lo), __uint_as_float(hi));
}
__device__ __forceinline__ u64 pack2(float lo, float hi) {
    u64 v; asm("mov.b64 %0, {%1, %2};" : "=l"(v) : "f"(lo), "f"(hi)); return v;
}
__device__ __forceinline__ u64 ffma2(u64 a, u64 b, u64 c) {
    u64 d; asm("fma.rn.f32x2 %0, %1, %2, %3;" : "=l"(d) : "l"(a), "l"(b), "l"(c)); return d;
}
__device__ __forceinline__ u64 addf2(u64 a, u64 b) {
    u64 d; asm("add.rn.f32x2 %0, %1, %2;" : "=l"(d) : "l"(a), "l"(b)); return d;
}
__device__ __forceinline__ float sigm_(float x) {
    return __fdividef(1.0f, 1.0f + __expf(-x));
}
__device__ __forceinline__ float tanh_(float x) {
    return __fdividef(2.0f, 1.0f + __expf(-2.0f * x)) - 1.0f;
}

// ---------------- barrier primitives ----------------
__device__ __forceinline__ unsigned atomAddRelease(unsigned* p, unsigned v) {
    unsigned o;
    asm volatile("atom.add.release.gpu.u32 %0, [%1], %2;"
                 : "=r"(o) : "l"(p), "r"(v) : "memory");
    return o;
}
__device__ __forceinline__ unsigned ldAcquire(unsigned* p) {
    unsigned o;
    asm volatile("ld.acquire.gpu.u32 %0, [%1];" : "=r"(o) : "l"(p) : "memory");
    return o;
}

// ---------------- init: zero h0 (transposed buf 0) + barrier counters ----------------
__global__ void init_state() {
    int i = blockIdx.x * blockDim.x + threadIdx.x;
    if (i < HID * 256) g_hT[0][i] = 0.0f;
    if (i == 0) { g_arrive = 0u; g_epoch = 0u; }
}

// ---------------- repack weights into gate-interleaved [n][k] ----------------
__global__ void repack(const float* __restrict__ Wf, const float* __restrict__ bf,
                       const float* __restrict__ Wi, const float* __restrict__ bi,
                       const float* __restrict__ Wc, const float* __restrict__ bc,
                       const float* __restrict__ Wo, const float* __restrict__ bo) {
    int idx = blockIdx.x * blockDim.x + threadIdx.x;
    if (idx >= NGATE * KDIM) return;
    int n = idx >> 10;           // n = j0*4 + gate
    int k = idx & 1023;
    int j0 = n >> 2;
    int g  = n & 3;
    const float* W = (g == 0) ? Wf : (g == 1) ? Wi : (g == 2) ? Wc : Wo;
    g_Wh[idx] = W[(size_t)j0 * 2048 + k];          // cols [0,H) act on h
    g_Wx[idx] = W[(size_t)j0 * 2048 + 1024 + k];   // cols [H,H+I) act on x
    if (k == 0) {
        const float* b = (g == 0) ? bf : (g == 1) ? bi : (g == 2) ? bc : bo;
        g_bias[n] = b[j0];
    }
}

// ---------------- precompute GEMM: Gx[m][n] = bias[n] + sum_k x[m][k]*Wx[n][k] ----------------
template<int BM, int BN, int BK, int TM, int TN>
__global__ __launch_bounds__(256) void gemm_pre(const float* __restrict__ A) {
    constexpr int TX = BN / TN;
    const int tid = threadIdx.x;
    const int tn  = tid % TX;
    const int tm  = tid / TX;
    const int n0  = blockIdx.x * BN;
    const int m0  = blockIdx.y * BM;

    __shared__ float As[BK][BM + 4];
    __shared__ float Bs[BK][BN + 4];

    u64 acc[TM][TN / 2];
#pragma unroll
    for (int i = 0; i < TM; ++i)
#pragma unroll
        for (int j = 0; j < TN / 2; ++j) acc[i][j] = 0ull;

    const float* Ab = A + (size_t)m0 * KDIM;
    const float* Wb = g_Wx + (size_t)n0 * KDIM;

    for (int k0 = 0; k0 < KDIM; k0 += BK) {
#pragma unroll
        for (int it = 0; it < (BM * BK / 4) / 256; ++it) {
            int id  = tid + it * 256;
            int row = id >> 2;
            int kq  = (id & 3) * 4;
            const float4 v = *reinterpret_cast<const float4*>(Ab + (size_t)row * KDIM + k0 + kq);
            As[kq + 0][row] = v.x; As[kq + 1][row] = v.y;
            As[kq + 2][row] = v.z; As[kq + 3][row] = v.w;
        }
#pragma unroll
        for (int it = 0; it < (BN * BK / 4) / 256; ++it) {
            int id  = tid + it * 256;
            int row = id >> 2;
            int kq  = (id & 3) * 4;
            const float4 v = *reinterpret_cast<const float4*>(Wb + (size_t)row * KDIM + k0 + kq);
            Bs[kq + 0][row] = v.x; Bs[kq + 1][row] = v.y;
            Bs[kq + 2][row] = v.z; Bs[kq + 3][row] = v.w;
        }
        __syncthreads();

#pragma unroll
        for (int kk = 0; kk < BK; ++kk) {
            float a[TM];
#pragma unroll
            for (int i = 0; i < TM / 4; ++i) {
                float4 v = *reinterpret_cast<const float4*>(&As[kk][tm * TM + i * 4]);
                a[i * 4 + 0] = v.x; a[i * 4 + 1] = v.y;
                a[i * 4 + 2] = v.z; a[i * 4 + 3] = v.w;
            }
            u64 bv[TN / 2];
#pragma unroll
            for (int j = 0; j < TN / 4; ++j) {
                const u64* p = reinterpret_cast<const u64*>(&Bs[kk][tn * TN + j * 4]);
                bv[j * 2 + 0] = p[0];
                bv[j * 2 + 1] = p[1];
            }
#pragma unroll
            for (int i = 0; i < TM; ++i) {
                u64 a2 = pack2(a[i], a[i]);
#pragma unroll
                for (int j = 0; j < TN / 2; ++j) acc[i][j] = ffma2(a2, bv[j], acc[i][j]);
            }
        }
        __syncthreads();
    }

#pragma unroll
    for (int i = 0; i < TM; ++i) {
        const int m = m0 + tm * TM + i;
        const int n = n0 + tn * TN;
        float* cp = g_Gx + (size_t)m * NGATE + n;
#pragma unroll
        for (int j = 0; j < TN / 4; ++j) {
            float4 bvv = *reinterpret_cast<const float4*>(g_bias + n + j * 4);
            float2 p0 = unpack2(acc[i][j * 2 + 0]);
            float2 p1 = unpack2(acc[i][j * 2 + 1]);
            float4 o;
            o.x = p0.x + bvv.x; o.y = p0.y + bvv.y;
            o.z = p1.x + bvv.z; o.w = p1.y + bvv.w;
            *reinterpret_cast<float4*>(cp + j * 4) = o;
        }
    }
}

// ---------------- persistent recurrence ----------------
// Block b owns 32 gate-cols (= 8 hidden units) for all 128 batches.
// Wh slice (k-major) resident in SMEM. h lives in global transposed+duplicated:
//   g_hT[j][2b] = g_hT[j][2b+1] = h[b][j]  -> staged by pure LDG128/STS128 copies,
//   consumed as ready-packed f32x2 operands (zero packing instructions in the hot loop).
// 512 threads: group g = tid>>8 handles K-half g; 4-row x 4-gate register tile;
// cross-group reduce via SMEM add.rn.f32x2. c-state register-resident.
__global__ __launch_bounds__(NT, 1) void lstm_persist(float* __restrict__ yout) {
    extern __shared__ float sm[];
    float* Ws = sm;                 // [1024][32] k-major weight slice (128 KB)
    float* hs = sm + 32 * KDIM;     // [64][P2]  staged dup-transposed h slab (65 KB)

    const int tid = threadIdx.x;
    const int g   = tid >> 8;       // K-half
    const int p   = tid & 255;      // pair id
    const int tn  = p & 7;          // hidden unit within block (8)
    const int tm  = p >> 3;         // 0..31 -> rows 4tm..4tm+3
    const int n0  = blockIdx.x * 32;
    const int j   = (n0 >> 2) + tn; // global hidden unit
    const int r0  = 4 * tm;

    // --- one-time: Wh slice -> SMEM k-major ---
    for (int it = 0; it < 16; ++it) {
        int id  = tid + it * NT;        // 8192 float4
        int col = id & 31;
        int kq  = (id >> 5) * 4;
        float4 v = *reinterpret_cast<const float4*>(&g_Wh[(size_t)(n0 + col) * KDIM + kq]);
        Ws[(kq + 0) * 32 + col] = v.x;
        Ws[(kq + 1) * 32 + col] = v.y;
        Ws[(kq + 2) * 32 + col] = v.z;
        Ws[(kq + 3) * 32 + col] = v.w;
    }
    __syncthreads();

    float c0 = 0.f, c1 = 0.f, c2 = 0.f, c3 = 0.f;  // cell state (group0 threads)

    for (int t = 0; t < S_LEN; ++t) {
        const float* hcurT = g_hT[t & 1];
        float*       hnxtT = g_hT[(t + 1) & 1];

        // prefetch Gx for epilogue (group0 only)
        float4 gx0, gx1, gx2, gx3;
        if (g == 0) {
            const float* gp = g_Gx + ((size_t)r0 * S_LEN + t) * NGATE + n0 + tn * 4;
            gx0 = *reinterpret_cast<const float4*>(gp);
            gx1 = *reinterpret_cast<const float4*>(gp + (size_t)S_LEN * NGATE);
            gx2 = *reinterpret_cast<const float4*>(gp + 2 * (size_t)S_LEN * NGATE);
            gx3 = *reinterpret_cast<const float4*>(gp + 3 * (size_t)S_LEN * NGATE);
        }

        // prefetch chunk 0 (64 k-rows x 256 dup-floats = 4096 float4 / 512 thr = 8 each)
        float4 pf[8];
#pragma unroll
        for (int it = 0; it < 8; ++it) {
            int idx = tid + it * NT;
            int sk  = idx >> 6;
            int f4  = idx & 63;
            int kabs = (sk < 32) ? sk : (512 + (sk - 32));
            pf[it] = __ldcg(reinterpret_cast<const float4*>(
                         hcurT + (size_t)kabs * 256 + f4 * 4));
        }

        u64 a0c0 = 0, a0c1 = 0, a1c0 = 0, a1c1 = 0;
        u64 a2c0 = 0, a2c1 = 0, a3c0 = 0, a3c1 = 0;

        for (int c = 0; c < 16; ++c) {
            __syncthreads();            // previous chunk's compute done reading hs
#pragma unroll
            for (int it = 0; it < 8; ++it) {
                int idx = tid + it * NT;
                int sk  = idx >> 6;
                int f4  = idx & 63;
                *reinterpret_cast<float4*>(&hs[sk * P2 + f4 * 4]) = pf[it];
            }
            __syncthreads();
            if (c < 15) {
#pragma unroll
                for (int it = 0; it < 8; ++it) {
                    int idx = tid + it * NT;
                    int sk  = idx >> 6;
                    int f4  = idx & 63;
                    int kabs = (sk < 32) ? ((c + 1) * 32 + sk)
                                         : (512 + (c + 1) * 32 + (sk - 32));
                    pf[it] = __ldcg(reinterpret_cast<const float4*>(
                                 hcurT + (size_t)kabs * 256 + f4 * 4));
                }
            }

            const float* hp = hs + (g * 32) * P2 + 8 * tm;
            const float* wp = Ws + ((g * 512 + c * 32) << 5) + 4 * tn;
#pragma unroll
            for (int kk = 0; kk < 32; ++kk) {
                ulonglong2 a01 = *reinterpret_cast<const ulonglong2*>(hp + kk * P2);
                ulonglong2 a23 = *reinterpret_cast<const ulonglong2*>(hp + kk * P2 + 4);
                ulonglong2 bb  = *reinterpret_cast<const ulonglong2*>(wp + kk * 32);
                a0c0 = ffma2(a01.x, bb.x, a0c0);
                a0c1 = ffma2(a01.x, bb.y, a0c1);
                a1c0 = ffma2(a01.y, bb.x, a1c0);
                a1c1 = ffma2(a01.y, bb.y, a1c1);
                a2c0 = ffma2(a23.x, bb.x, a2c0);
                a2c1 = ffma2(a23.x, bb.y, a2c1);
                a3c0 = ffma2(a23.y, bb.x, a3c0);
                a3c1 = ffma2(a23.y, bb.y, a3c1);
            }
        }

        // --- cross-group reduce through SMEM (80B stride: conflict-free) ---
        u64* red = reinterpret_cast<u64*>(hs);
        if (g == 1) {
            ulonglong2* rp = reinterpret_cast<ulonglong2*>(red + p * 10);
            rp[0] = make_ulonglong2(a0c0, a0c1);
            rp[1] = make_ulonglong2(a1c0, a1c1);
            rp[2] = make_ulonglong2(a2c0, a2c1);
            rp[3] = make_ulonglong2(a3c0, a3c1);
        }
        __syncthreads();
        if (g == 0) {
            const ulonglong2* rp = reinterpret_cast<const ulonglong2*>(red + p * 10);
            ulonglong2 q0 = rp[0], q1 = rp[1], q2 = rp[2], q3 = rp[3];
            a0c0 = addf2(a0c0, q0.x); a0c1 = addf2(a0c1, q0.y);
            a1c0 = addf2(a1c0, q1.x); a1c1 = addf2(a1c1, q1.y);
            a2c0 = addf2(a2c0, q2.x); a2c1 = addf2(a2c1, q2.y);
            a3c0 = addf2(a3c0, q3.x); a3c1 = addf2(a3c1, q3.y);

            // --- LSTM cell epilogue: 4 rows x (f,i,g,o) ---
            float2 fi, go;
            float h0v, h1v, h2v, h3v;

            fi = unpack2(a0c0); go = unpack2(a0c1);
            {
                float fg = sigm_(fi.x + gx0.x), ig = sigm_(fi.y + gx0.y);
                float gg = tanh_(go.x + gx0.z), og = sigm_(go.y + gx0.w);
                c0 = c0 * fg + ig * gg;  h0v = tanh_(c0) * og;
            }
            fi = unpack2(a1c0); go = unpack2(a1c1);
            {
                float fg = sigm_(fi.x + gx1.x), ig = sigm_(fi.y + gx1.y);
                float gg = tanh_(go.x + gx1.z), og = sigm_(go.y + gx1.w);
                c1 = c1 * fg + ig * gg;  h1v = tanh_(c1) * og;
            }
            fi = unpack2(a2c0); go = unpack2(a2c1);
            {
                float fg = sigm_(fi.x + gx2.x), ig = sigm_(fi.y + gx2.y);
                float gg = tanh_(go.x + gx2.z), og = sigm_(go.y + gx2.w);
                c2 = c2 * fg + ig * gg;  h2v = tanh_(c2) * og;
            }
            fi = unpack2(a3c0); go = unpack2(a3c1);
            {
                float fg = sigm_(fi.x + gx3.x), ig = sigm_(fi.y + gx3.y);
                float gg = tanh_(go.x + gx3.z), og = sigm_(go.y + gx3.w);
                c3 = c3 * fg + ig * gg;  h3v = tanh_(c3) * og;
            }

            // h -> global transposed+duplicated (ready-packed for next step)
            float* hp0 = hnxtT + (size_t)j * 256 + 2 * r0;
            __stcg(reinterpret_cast<float4*>(hp0),     make_float4(h0v, h0v, h1v, h1v));
            __stcg(reinterpret_cast<float4*>(hp0 + 4), make_float4(h2v, h2v, h3v, h3v));

            // output [B][S][H]
            yout[((size_t)(r0 + 0) * S_LEN + t) * HID + j] = h0v;
            yout[((size_t)(r0 + 1) * S_LEN + t) * HID + j] = h1v;
            yout[((size_t)(r0 + 2) * S_LEN + t) * HID + j] = h2v;
            yout[((size_t)(r0 + 3) * S_LEN + t) * HID + j] = h3v;
        }

        // --- grid barrier (release/acquire; no per-thread membar) ---
        __syncthreads();   // epilogue stores ordered before tid0's release-arrive
        if (tid == 0) {
            unsigned old = atomAddRelease(&g_arrive, 1u);
            if (old == NB - 1) {
                asm volatile("st.global.relaxed.gpu.u32 [%0], %1;"
                             :: "l"(&g_arrive), "r"(0u) : "memory");
                atomAddRelease(&g_epoch, 1u);
            } else {
                unsigned target = (unsigned)t + 1u;
                while (ldAcquire(&g_epoch) < target) {}
            }
        }
        __syncthreads();   // propagate acquire to all threads
    }
}

// ---------------- launch ----------------
extern "C" void kernel_launch(void* const* d_in, const int* in_sizes, int n_in,
                              void* d_out, int out_size) {
    const float* x  = (const float*)d_in[0];
    const float* Wf = (const float*)d_in[1]; const float* bf = (const float*)d_in[2];
    const float* Wi = (const float*)d_in[3]; const float* bi = (const float*)d_in[4];
    const float* Wc = (const float*)d_in[5]; const float* bc = (const float*)d_in[6];
    const float* Wo = (const float*)d_in[7]; const float* bo = (const float*)d_in[8];
    float* out = (float*)d_out;

    init_state<<<(HID * 256 + 255) / 256, 256>>>();
    repack<<<(NGATE * KDIM + 255) / 256, 256>>>(Wf, bf, Wi, bi, Wc, bc, Wo, bo);

    // Precompute Gx = bias + x @ Wx^T for all (b,t): M=32768, N=4096
    gemm_pre<128, 128, 16, 8, 8>
        <<<dim3(NGATE / 128, (BATCH * S_LEN) / 128), 256>>>(x);

    // Persistent recurrence: whole 256-step scan in one kernel
    const int smem_bytes = (32 * KDIM + 64 * P2) * (int)sizeof(float);  // 197632 B
    cudaFuncSetAttribute(lstm_persist, cudaFuncAttributeMaxDynamicSharedMemorySize, smem_bytes);
    lstm_persist<<<NB, NT, smem_bytes>>>(out);
}

// round 10
// speedup vs baseline: 1.1548x; 1.0061x over previous
#include <cuda_runtime.h>
#include <cstdint>
#include <math.h>

#define S_LEN 256
#define HID   1024
#define BATCH 128
#define NGATE 4096   // 4 * HID, gate-interleaved: n = j0*4 + gate (f,i,g,o)
#define KDIM  1024

#define NB 128       // persistent blocks (all co-resident; 1 per SM)
#define NT 1024      // threads per persistent block (8 warps/SMSP)
#define P2 260       // hs pitch in floats (mult of 4 -> 16B aligned rows)
#define RSTRIDE 10   // reduce stride in u64 (80B: multiple of 16 -> ST.128 legal)

typedef unsigned long long u64;

// ---------------- device scratch (no allocs allowed) ----------------
__device__ float g_Wx[(size_t)NGATE * KDIM];          // x-part weights, [n][k]
__device__ float g_Wh[(size_t)NGATE * KDIM];          // h-part weights, [n][k]
__device__ float g_bias[NGATE];
__device__ float g_Gx[(size_t)BATCH * S_LEN * NGATE]; // bias + x@Wx^T, row m=b*S+t
__device__ float g_hT[2][(size_t)HID * 256];          // h transposed + duplicated: [j][2b],[2b+1]
__device__ unsigned g_arrive;
__device__ unsigned g_epoch;

// ---------------- f32x2 helpers ----------------
__device__ __forceinline__ float2 unpack2(u64 v) {
    unsigned lo, hi;
    asm("mov.b64 {%0, %1}, %2;" : "=r"(lo), "=r"(hi) : "l"(v));
    return make_float2(__uint_as_float(lo), __uint_as_float(hi));
}
__device__ __forceinline__ u64 pack2(float lo, float hi) {
    u64 v; asm("mov.b64 %0, {%1, %2};" : "=l"(v) : "f"(lo), "f"(hi)); return v;
}
__device__ __forceinline__ u64 ffma2(u64 a, u64 b, u64 c) {
    u64 d; asm("fma.rn.f32x2 %0, %1, %2, %3;" : "=l"(d) : "l"(a), "l"(b), "l"(c)); return d;
}
__device__ __forceinline__ u64 addf2(u64 a, u64 b) {
    u64 d; asm("add.rn.f32x2 %0, %1, %2;" : "=l"(d) : "l"(a), "l"(b)); return d;
}
__device__ __forceinline__ float sigm_(float x) {
    return __fdividef(1.0f, 1.0f + __expf(-x));
}
__device__ __forceinline__ float tanh_(float x) {
    return __fdividef(2.0f, 1.0f + __expf(-2.0f * x)) - 1.0f;
}

// ---------------- barrier primitives ----------------
__device__ __forceinline__ unsigned atomAddRelease(unsigned* p, unsigned v) {
    unsigned o;
    asm volatile("atom.add.release.gpu.u32 %0, [%1], %2;"
                 : "=r"(o) : "l"(p), "r"(v) : "memory");
    return o;
}
__device__ __forceinline__ unsigned ldAcquire(unsigned* p) {
    unsigned o;
    asm volatile("ld.acquire.gpu.u32 %0, [%1];" : "=r"(o) : "l"(p) : "memory");
    return o;
}

// ---------------- init: zero h0 (transposed buf 0) + barrier counters ----------------
__global__ void init_state() {
    int i = blockIdx.x * blockDim.x + threadIdx.x;
    if (i < HID * 256) g_hT[0][i] = 0.0f;
    if (i == 0) { g_arrive = 0u; g_epoch = 0u; }
}

// ---------------- repack weights into gate-interleaved [n][k] ----------------
__global__ void repack(const float* __restrict__ Wf, const float* __restrict__ bf,
                       const float* __restrict__ Wi, const float* __restrict__ bi,
                       const float* __restrict__ Wc, const float* __restrict__ bc,
                       const float* __restrict__ Wo, const float* __restrict__ bo) {
    int idx = blockIdx.x * blockDim.x + threadIdx.x;
    if (idx >= NGATE * KDIM) return;
    int n = idx >> 10;           // n = j0*4 + gate
    int k = idx & 1023;
    int j0 = n >> 2;
    int g  = n & 3;
    const float* W = (g == 0) ? Wf : (g == 1) ? Wi : (g == 2) ? Wc : Wo;
    g_Wh[idx] = W[(size_t)j0 * 2048 + k];          // cols [0,H) act on h
    g_Wx[idx] = W[(size_t)j0 * 2048 + 1024 + k];   // cols [H,H+I) act on x
    if (k == 0) {
        const float* b = (g == 0) ? bf : (g == 1) ? bi : (g == 2) ? bc : bo;
        g_bias[n] = b[j0];
    }
}

// ---------------- precompute GEMM: Gx[m][n] = bias[n] + sum_k x[m][k]*Wx[n][k] ----------------
template<int BM, int BN, int BK, int TM, int TN>
__global__ __launch_bounds__(256) void gemm_pre(const float* __restrict__ A) {
    constexpr int TX = BN / TN;
    const int tid = threadIdx.x;
    const int tn  = tid % TX;
    const int tm  = tid / TX;
    const int n0  = blockIdx.x * BN;
    const int m0  = blockIdx.y * BM;

    __shared__ float As[BK][BM + 4];
    __shared__ float Bs[BK][BN + 4];

    u64 acc[TM][TN / 2];
#pragma unroll
    for (int i = 0; i < TM; ++i)
#pragma unroll
        for (int j = 0; j < TN / 2; ++j) acc[i][j] = 0ull;

    const float* Ab = A + (size_t)m0 * KDIM;
    const float* Wb = g_Wx + (size_t)n0 * KDIM;

    for (int k0 = 0; k0 < KDIM; k0 += BK) {
#pragma unroll
        for (int it = 0; it < (BM * BK / 4) / 256; ++it) {
            int id  = tid + it * 256;
            int row = id >> 2;
            int kq  = (id & 3) * 4;
            const float4 v = *reinterpret_cast<const float4*>(Ab + (size_t)row * KDIM + k0 + kq);
            As[kq + 0][row] = v.x; As[kq + 1][row] = v.y;
            As[kq + 2][row] = v.z; As[kq + 3][row] = v.w;
        }
#pragma unroll
        for (int it = 0; it < (BN * BK / 4) / 256; ++it) {
            int id  = tid + it * 256;
            int row = id >> 2;
            int kq  = (id & 3) * 4;
            const float4 v = *reinterpret_cast<const float4*>(Wb + (size_t)row * KDIM + k0 + kq);
            Bs[kq + 0][row] = v.x; Bs[kq + 1][row] = v.y;
            Bs[kq + 2][row] = v.z; Bs[kq + 3][row] = v.w;
        }
        __syncthreads();

#pragma unroll
        for (int kk = 0; kk < BK; ++kk) {
            float a[TM];
#pragma unroll
            for (int i = 0; i < TM / 4; ++i) {
                float4 v = *reinterpret_cast<const float4*>(&As[kk][tm * TM + i * 4]);
                a[i * 4 + 0] = v.x; a[i * 4 + 1] = v.y;
                a[i * 4 + 2] = v.z; a[i * 4 + 3] = v.w;
            }
            u64 bv[TN / 2];
#pragma unroll
            for (int j = 0; j < TN / 4; ++j) {
                const u64* p = reinterpret_cast<const u64*>(&Bs[kk][tn * TN + j * 4]);
                bv[j * 2 + 0] = p[0];
                bv[j * 2 + 1] = p[1];
            }
#pragma unroll
            for (int i = 0; i < TM; ++i) {
                u64 a2 = pack2(a[i], a[i]);
#pragma unroll
                for (int j = 0; j < TN / 2; ++j) acc[i][j] = ffma2(a2, bv[j], acc[i][j]);
            }
        }
        __syncthreads();
    }

#pragma unroll
    for (int i = 0; i < TM; ++i) {
        const int m = m0 + tm * TM + i;
        const int n = n0 + tn * TN;
        float* cp = g_Gx + (size_t)m * NGATE + n;
#pragma unroll
        for (int j = 0; j < TN / 4; ++j) {
            float4 bvv = *reinterpret_cast<const float4*>(g_bias + n + j * 4);
            float2 p0 = unpack2(acc[i][j * 2 + 0]);
            float2 p1 = unpack2(acc[i][j * 2 + 1]);
            float4 o;
            o.x = p0.x + bvv.x; o.y = p0.y + bvv.y;
            o.z = p1.x + bvv.z; o.w = p1.y + bvv.w;
            *reinterpret_cast<float4*>(cp + j * 4) = o;
        }
    }
}

// ---------------- persistent recurrence ----------------
// Block b owns 32 gate-cols (= 8 hidden units) for all 128 batches.
// Wh slice (k-major) resident in SMEM. h in global, transposed + duplicated:
//   g_hT[j][2b] = g_hT[j][2b+1] = h[b][j]  -> pure LDG128/STS128 staging, consumed
//   as ready-packed f32x2 operands. 1024 threads = 4 K-split groups of 256;
//   each thread: 4 batch rows x 1 hidden unit (8 ffma2 per kk). Cross-group
//   reduce via SMEM (80B stride, 16B-aligned). c-state register-resident in group 0.
__global__ __launch_bounds__(NT, 1) void lstm_persist(float* __restrict__ yout) {
    extern __shared__ float sm[];
    float* Ws = sm;                 // [1024][32] k-major weight slice (128 KB)
    float* hs = sm + 32 * KDIM;     // [64][P2]  staged dup-transposed h slab (~65 KB)

    const int tid = threadIdx.x;
    const int g   = tid >> 8;       // K-quarter (0..3)
    const int p   = tid & 255;
    const int tn  = p & 7;          // hidden unit within block (8)
    const int tm  = p >> 3;         // 0..31 -> rows 4tm..4tm+3
    const int n0  = blockIdx.x * 32;
    const int j   = (n0 >> 2) + tn; // global hidden unit
    const int r0  = 4 * tm;

    // --- one-time: Wh slice -> SMEM k-major ---
    for (int it = 0; it < 8; ++it) {
        int id  = tid + it * NT;        // 8192 float4
        int col = id & 31;
        int kq  = (id >> 5) * 4;
        float4 v = *reinterpret_cast<const float4*>(&g_Wh[(size_t)(n0 + col) * KDIM + kq]);
        Ws[(kq + 0) * 32 + col] = v.x;
        Ws[(kq + 1) * 32 + col] = v.y;
        Ws[(kq + 2) * 32 + col] = v.z;
        Ws[(kq + 3) * 32 + col] = v.w;
    }
    __syncthreads();

    float c0 = 0.f, c1 = 0.f, c2 = 0.f, c3 = 0.f;  // cell state (group-0 threads)

    for (int t = 0; t < S_LEN; ++t) {
        const float* hcurT = g_hT[t & 1];
        float*       hnxtT = g_hT[(t + 1) & 1];

        // prefetch chunk 0: 64 k-rows x 256 dup-floats = 4096 float4 / 1024 thr = 4 each
        // staged row sk belongs to group sk>>4; its global k = (sk>>4)*256 + c*16 + (sk&15)
        float4 pf[4];
#pragma unroll
        for (int it = 0; it < 4; ++it) {
            int idx = tid + it * NT;
            int sk  = idx >> 6;
            int f4  = idx & 63;
            int kabs = (sk >> 4) * 256 + (sk & 15);
            pf[it] = __ldcg(reinterpret_cast<const float4*>(
                         hcurT + (size_t)kabs * 256 + f4 * 4));
        }

        u64 a0c0 = 0, a0c1 = 0, a1c0 = 0, a1c1 = 0;
        u64 a2c0 = 0, a2c1 = 0, a3c0 = 0, a3c1 = 0;

        for (int c = 0; c < 16; ++c) {
            __syncthreads();            // previous chunk's compute done reading hs
#pragma unroll
            for (int it = 0; it < 4; ++it) {
                int idx = tid + it * NT;
                int sk  = idx >> 6;
                int f4  = idx & 63;
                *reinterpret_cast<float4*>(&hs[sk * P2 + f4 * 4]) = pf[it];
            }
            __syncthreads();
            if (c < 15) {
#pragma unroll
                for (int it = 0; it < 4; ++it) {
                    int idx = tid + it * NT;
                    int sk  = idx >> 6;
                    int f4  = idx & 63;
                    int kabs = (sk >> 4) * 256 + (c + 1) * 16 + (sk & 15);
                    pf[it] = __ldcg(reinterpret_cast<const float4*>(
                                 hcurT + (size_t)kabs * 256 + f4 * 4));
                }
            }

            const float* hp = hs + (g * 16) * P2 + 8 * tm;
            const float* wp = Ws + ((g * 256 + c * 16) << 5) + 4 * tn;
#pragma unroll
            for (int kk = 0; kk < 16; ++kk) {
                ulonglong2 a01 = *reinterpret_cast<const ulonglong2*>(hp + kk * P2);
                ulonglong2 a23 = *reinterpret_cast<const ulonglong2*>(hp + kk * P2 + 4);
                ulonglong2 bb  = *reinterpret_cast<const ulonglong2*>(wp + kk * 32);
                a0c0 = ffma2(a01.x, bb.x, a0c0);
                a0c1 = ffma2(a01.x, bb.y, a0c1);
                a1c0 = ffma2(a01.y, bb.x, a1c0);
                a1c1 = ffma2(a01.y, bb.y, a1c1);
                a2c0 = ffma2(a23.x, bb.x, a2c0);
                a2c1 = ffma2(a23.x, bb.y, a2c1);
                a3c0 = ffma2(a23.y, bb.x, a3c0);
                a3c1 = ffma2(a23.y, bb.y, a3c1);
            }
        }

        // all compute done reading hs before reduction reuses it
        __syncthreads();

        // --- cross-group reduce through SMEM (groups 1..3 -> group 0) ---
        // 80B per-thread stride: every ulonglong2 lands 16B-aligned.
        u64* red = reinterpret_cast<u64*>(hs);
        if (g >= 1) {
            ulonglong2* rp =
                reinterpret_cast<ulonglong2*>(red + ((g - 1) * 256 + p) * RSTRIDE);
            rp[0] = make_ulonglong2(a0c0, a0c1);
            rp[1] = make_ulonglong2(a1c0, a1c1);
            rp[2] = make_ulonglong2(a2c0, a2c1);
            rp[3] = make_ulonglong2(a3c0, a3c1);
        }
        __syncthreads();
        if (g == 0) {
            // Gx loads (DRAM) issued first; latency overlaps the reduce adds
            const float* gp = g_Gx + ((size_t)r0 * S_LEN + t) * NGATE + n0 + tn * 4;
            float4 gx0 = *reinterpret_cast<const float4*>(gp);
            float4 gx1 = *reinterpret_cast<const float4*>(gp + (size_t)S_LEN * NGATE);
            float4 gx2 = *reinterpret_cast<const float4*>(gp + 2 * (size_t)S_LEN * NGATE);
            float4 gx3 = *reinterpret_cast<const float4*>(gp + 3 * (size_t)S_LEN * NGATE);

#pragma unroll
            for (int s = 0; s < 3; ++s) {
                const ulonglong2* rp =
                    reinterpret_cast<const ulonglong2*>(red + (s * 256 + p) * RSTRIDE);
                ulonglong2 q0 = rp[0], q1 = rp[1], q2 = rp[2], q3 = rp[3];
                a0c0 = addf2(a0c0, q0.x); a0c1 = addf2(a0c1, q0.y);
                a1c0 = addf2(a1c0, q1.x); a1c1 = addf2(a1c1, q1.y);
                a2c0 = addf2(a2c0, q2.x); a2c1 = addf2(a2c1, q2.y);
                a3c0 = addf2(a3c0, q3.x); a3c1 = addf2(a3c1, q3.y);
            }

            // --- LSTM cell epilogue: 4 rows x (f,i,g,o) ---
            float2 fi, go;
            float h0v, h1v, h2v, h3v;

            fi = unpack2(a0c0); go = unpack2(a0c1);
            {
                float fg = sigm_(fi.x + gx0.x), ig = sigm_(fi.y + gx0.y);
                float gg = tanh_(go.x + gx0.z), og = sigm_(go.y + gx0.w);
                c0 = c0 * fg + ig * gg;  h0v = tanh_(c0) * og;
            }
            fi = unpack2(a1c0); go = unpack2(a1c1);
            {
                float fg = sigm_(fi.x + gx1.x), ig = sigm_(fi.y + gx1.y);
                float gg = tanh_(go.x + gx1.z), og = sigm_(go.y + gx1.w);
                c1 = c1 * fg + ig * gg;  h1v = tanh_(c1) * og;
            }
            fi = unpack2(a2c0); go = unpack2(a2c1);
            {
                float fg = sigm_(fi.x + gx2.x), ig = sigm_(fi.y + gx2.y);
                float gg = tanh_(go.x + gx2.z), og = sigm_(go.y + gx2.w);
                c2 = c2 * fg + ig * gg;  h2v = tanh_(c2) * og;
            }
            fi = unpack2(a3c0); go = unpack2(a3c1);
            {
                float fg = sigm_(fi.x + gx3.x), ig = sigm_(fi.y + gx3.y);
                float gg = tanh_(go.x + gx3.z), og = sigm_(go.y + gx3.w);
                c3 = c3 * fg + ig * gg;  h3v = tanh_(c3) * og;
            }

            // h -> global transposed+duplicated (ready-packed for next step)
            float* hp0 = hnxtT + (size_t)j * 256 + 2 * r0;
            __stcg(reinterpret_cast<float4*>(hp0),     make_float4(h0v, h0v, h1v, h1v));
            __stcg(reinterpret_cast<float4*>(hp0 + 4), make_float4(h2v, h2v, h3v, h3v));

            // output [B][S][H]
            yout[((size_t)(r0 + 0) * S_LEN + t) * HID + j] = h0v;
            yout[((size_t)(r0 + 1) * S_LEN + t) * HID + j] = h1v;
            yout[((size_t)(r0 + 2) * S_LEN + t) * HID + j] = h2v;
            yout[((size_t)(r0 + 3) * S_LEN + t) * HID + j] = h3v;
        }

        // --- grid barrier (release/acquire) ---
        __syncthreads();   // epilogue stores ordered before tid0's release-arrive
        if (tid == 0) {
            unsigned old = atomAddRelease(&g_arrive, 1u);
            if (old == NB - 1) {
                asm volatile("st.global.relaxed.gpu.u32 [%0], %1;"
                             :: "l"(&g_arrive), "r"(0u) : "memory");
                atomAddRelease(&g_epoch, 1u);
            } else {
                unsigned target = (unsigned)t + 1u;
                while (ldAcquire(&g_epoch) < target) {}
            }
        }
        __syncthreads();   // propagate acquire to all threads
    }
}

// ---------------- launch ----------------
extern "C" void kernel_launch(void* const* d_in, const int* in_sizes, int n_in,
                              void* d_out, int out_size) {
    const float* x  = (const float*)d_in[0];
    const float* Wf = (const float*)d_in[1]; const float* bf = (const float*)d_in[2];
    const float* Wi = (const float*)d_in[3]; const float* bi = (const float*)d_in[4];
    const float* Wc = (const float*)d_in[5]; const float* bc = (const float*)d_in[6];
    const float* Wo = (const float*)d_in[7]; const float* bo = (const float*)d_in[8];
    float* out = (float*)d_out;

    init_state<<<(HID * 256 + 255) / 256, 256>>>();
    repack<<<(NGATE * KDIM + 255) / 256, 256>>>(Wf, bf, Wi, bi, Wc, bc, Wo, bo);

    // Precompute Gx = bias + x @ Wx^T for all (b,t): M=32768, N=4096
    gemm_pre<128, 128, 16, 8, 8>
        <<<dim3(NGATE / 128, (BATCH * S_LEN) / 128), 256>>>(x);

    // Persistent recurrence: whole 256-step scan in one kernel
    const int smem_bytes = (32 * KDIM + 64 * P2) * (int)sizeof(float);  // 197632 B
    cudaFuncSetAttribute(lstm_persist, cudaFuncAttributeMaxDynamicSharedMemorySize, smem_bytes);
    lstm_persist<<<NB, NT, smem_bytes>>>(out);
}

// round 12
// speedup vs baseline: 1.2182x; 1.0549x over previous
#include <cuda_runtime.h>
#include <cuda_bf16.h>
#include <cstdint>
#include <math.h>

#define S_LEN 256
#define HID   1024
#define BATCH 128
#define NGATE 4096   // 4 * HID, gate-interleaved: n = j0*4 + gate (f,i,g,o)
#define KDIM  1024

#define NB 128       // persistent blocks (all co-resident; 1 per SM)
#define NT 512       // threads per persistent block (16 warps)

typedef unsigned long long u64;

// ---------------- device scratch (no allocs allowed) ----------------
__device__ float g_Wx[(size_t)NGATE * KDIM];          // x-part weights fp32, [n][k]
__device__ float g_bias[NGATE];
__device__ float g_Gx[(size_t)BATCH * S_LEN * NGATE]; // bias + x@Wx^T, row m=b*S+t

// Wh split (bf16 hi/lo) in mma-fragment-native layout:
//   [block(128)][term(2)][kb(64)][c(32)][tg(4)] 8B-units; unit holds bf16 at
//   k-offsets {2tg, 2tg+1, 2tg+8, 2tg+9} of k-block kb, gate-col c of the block.
__device__ float4 g_Whf[(size_t)128 * 2 * 64 * 32 * 2];   // 16 MB

// h split (bf16 hi/lo), ping-pong, fragment-native:
//   [pp(2)][term(2)][kb(64)][row(128)][tg(4)] 8B-units, same unit semantics (k = hidden j).
__device__ float4 g_hf[(size_t)2 * 2 * 64 * 128 * 2];     // 2 MB

__device__ unsigned g_arrive;
__device__ unsigned g_epoch;

// ---------------- helpers ----------------
__device__ __forceinline__ float2 unpack2(u64 v) {
    unsigned lo, hi;
    asm("mov.b64 {%0, %1}, %2;" : "=r"(lo), "=r"(hi) : "l"(v));
    return make_float2(__uint_as_float(lo), __uint_as_float(hi));
}
__device__ __forceinline__ u64 pack2(float lo, float hi) {
    u64 v; asm("mov.b64 %0, {%1, %2};" : "=l"(v) : "f"(lo), "f"(hi)); return v;
}
__device__ __forceinline__ u64 ffma2(u64 a, u64 b, u64 c) {
    u64 d; asm("fma.rn.f32x2 %0, %1, %2, %3;" : "=l"(d) : "l"(a), "l"(b), "l"(c)); return d;
}
__device__ __forceinline__ float sigm_(float x) {
    return __fdividef(1.0f, 1.0f + __expf(-x));
}
__device__ __forceinline__ float tanh_(float x) {
    return __fdividef(2.0f, 1.0f + __expf(-2.0f * x)) - 1.0f;
}
__device__ __forceinline__ unsigned atomAddRelease(unsigned* p, unsigned v) {
    unsigned o;
    asm volatile("atom.add.release.gpu.u32 %0, [%1], %2;"
                 : "=r"(o) : "l"(p), "r"(v) : "memory");
    return o;
}
__device__ __forceinline__ unsigned ldAcquire(unsigned* p) {
    unsigned o;
    asm volatile("ld.acquire.gpu.u32 %0, [%1];" : "=r"(o) : "l"(p) : "memory");
    return o;
}
__device__ __forceinline__ void st_cg_b16(void* p, __nv_bfloat16 v) {
    unsigned short u = *reinterpret_cast<unsigned short*>(&v);
    asm volatile("st.global.cg.u16 [%0], %1;" :: "l"(p), "h"(u) : "memory");
}

// m16n8k16 row.col bf16 mma, fp32 accumulate (D==C in-place)
#define MMA16816(dd, aa, bb)                                                     \
    asm volatile(                                                                \
        "mma.sync.aligned.m16n8k16.row.col.f32.bf16.bf16.f32 "                   \
        "{%0,%1,%2,%3},{%4,%5,%6,%7},{%8,%9},{%0,%1,%2,%3};"                     \
        : "+f"((dd)[0]), "+f"((dd)[1]), "+f"((dd)[2]), "+f"((dd)[3])             \
        : "r"((aa)[0]), "r"((aa)[1]), "r"((aa)[2]), "r"((aa)[3]),                \
          "r"((bb)[0]), "r"((bb)[1]))

// (tg,p) position of hidden-index-within-16 jj inside an 8B fragment unit
__device__ __forceinline__ void jj_to_tgp(int jj, int& tg, int& p) {
    if (jj < 8) { tg = jj >> 1; p = jj & 1; }
    else        { tg = (jj >> 1) - 4; p = 2 + (jj & 1); }
}

// ---------------- init: zero h0 fragment buffer (pp=0) + barrier counters ----------------
__global__ void init_state() {
    int i = blockIdx.x * blockDim.x + threadIdx.x;
    if (i < 2 * 16384) g_hf[i] = make_float4(0.f, 0.f, 0.f, 0.f);  // pp=0: 2 terms x 16384 f4
    if (i == 0) { g_arrive = 0u; g_epoch = 0u; }
}

// ---------------- repack: x-weights fp32 [n][k] + bias + Wh bf16-split frag layout ----------
__global__ void repack(const float* __restrict__ Wf, const float* __restrict__ bf,
                       const float* __restrict__ Wi, const float* __restrict__ bi,
                       const float* __restrict__ Wc, const float* __restrict__ bc,
                       const float* __restrict__ Wo, const float* __restrict__ bo) {
    int idx = blockIdx.x * blockDim.x + threadIdx.x;
    if (idx >= NGATE * KDIM) return;
    int n = idx >> 10;           // n = j0*4 + gate
    int k = idx & 1023;
    int j0 = n >> 2;
    int g  = n & 3;
    const float* W = (g == 0) ? Wf : (g == 1) ? Wi : (g == 2) ? Wc : Wo;
    float vh = W[(size_t)j0 * 2048 + k];           // cols [0,H) act on h
    g_Wx[idx] = W[(size_t)j0 * 2048 + 1024 + k];   // cols [H,H+I) act on x
    if (k == 0) {
        const float* b = (g == 0) ? bf : (g == 1) ? bi : (g == 2) ? bc : bo;
        g_bias[n] = b[j0];
    }
    // bf16 split of the h-part weight into fragment layout
    __nv_bfloat16 w1 = __float2bfloat16(vh);
    __nv_bfloat16 w2 = __float2bfloat16(vh - __bfloat162float(w1));
    int blk = n >> 5;
    int c   = n & 31;
    int kb  = k >> 4;
    int tg, p; jj_to_tgp(k & 15, tg, p);
    __nv_bfloat16* base = reinterpret_cast<__nv_bfloat16*>(g_Whf);
    size_t u1 = ((((size_t)blk * 2 + 0) * 64 + kb) * 32 + c) * 4 + tg;
    size_t u2 = ((((size_t)blk * 2 + 1) * 64 + kb) * 32 + c) * 4 + tg;
    base[u1 * 4 + p] = w1;
    base[u2 * 4 + p] = w2;
}

// ---------------- precompute GEMM: Gx[m][n] = bias[n] + sum_k x[m][k]*Wx[n][k] ----------------
template<int BM, int BN, int BK, int TM, int TN>
__global__ __launch_bounds__(256) void gemm_pre(const float* __restrict__ A) {
    constexpr int TX = BN / TN;
    const int tid = threadIdx.x;
    const int tn  = tid % TX;
    const int tm  = tid / TX;
    const int n0  = blockIdx.x * BN;
    const int m0  = blockIdx.y * BM;

    __shared__ float As[BK][BM + 4];
    __shared__ float Bs[BK][BN + 4];

    u64 acc[TM][TN / 2];
#pragma unroll
    for (int i = 0; i < TM; ++i)
#pragma unroll
        for (int j = 0; j < TN / 2; ++j) acc[i][j] = 0ull;

    const float* Ab = A + (size_t)m0 * KDIM;
    const float* Wb = g_Wx + (size_t)n0 * KDIM;

    for (int k0 = 0; k0 < KDIM; k0 += BK) {
#pragma unroll
        for (int it = 0; it < (BM * BK / 4) / 256; ++it) {
            int id  = tid + it * 256;
            int row = id >> 2;
            int kq  = (id & 3) * 4;
            const float4 v = *reinterpret_cast<const float4*>(Ab + (size_t)row * KDIM + k0 + kq);
            As[kq + 0][row] = v.x; As[kq + 1][row] = v.y;
            As[kq + 2][row] = v.z; As[kq + 3][row] = v.w;
        }
#pragma unroll
        for (int it = 0; it < (BN * BK / 4) / 256; ++it) {
            int id  = tid + it * 256;
            int row = id >> 2;
            int kq  = (id & 3) * 4;
            const float4 v = *reinterpret_cast<const float4*>(Wb + (size_t)row * KDIM + k0 + kq);
            Bs[kq + 0][row] = v.x; Bs[kq + 1][row] = v.y;
            Bs[kq + 2][row] = v.z; Bs[kq + 3][row] = v.w;
        }
        __syncthreads();

#pragma unroll
        for (int kk = 0; kk < BK; ++kk) {
            float a[TM];
#pragma unroll
            for (int i = 0; i < TM / 4; ++i) {
                float4 v = *reinterpret_cast<const float4*>(&As[kk][tm * TM + i * 4]);
                a[i * 4 + 0] = v.x; a[i * 4 + 1] = v.y;
                a[i * 4 + 2] = v.z; a[i * 4 + 3] = v.w;
            }
            u64 bv[TN / 2];
#pragma unroll
            for (int j = 0; j < TN / 4; ++j) {
                const u64* p = reinterpret_cast<const u64*>(&Bs[kk][tn * TN + j * 4]);
                bv[j * 2 + 0] = p[0];
                bv[j * 2 + 1] = p[1];
            }
#pragma unroll
            for (int i = 0; i < TM; ++i) {
                u64 a2 = pack2(a[i], a[i]);
#pragma unroll
                for (int j = 0; j < TN / 2; ++j) acc[i][j] = ffma2(a2, bv[j], acc[i][j]);
            }
        }
        __syncthreads();
    }

#pragma unroll
    for (int i = 0; i < TM; ++i) {
        const int m = m0 + tm * TM + i;
        const int n = n0 + tn * TN;
        float* cp = g_Gx + (size_t)m * NGATE + n;
#pragma unroll
        for (int j = 0; j < TN / 4; ++j) {
            float4 bvv = *reinterpret_cast<const float4*>(g_bias + n + j * 4);
            float2 p0 = unpack2(acc[i][j * 2 + 0]);
            float2 p1 = unpack2(acc[i][j * 2 + 1]);
            float4 o;
            o.x = p0.x + bvv.x; o.y = p0.y + bvv.y;
            o.z = p1.x + bvv.z; o.w = p1.y + bvv.w;
            *reinterpret_cast<float4*>(cp + j * 4) = o;
        }
    }
}

// ---------------- persistent recurrence: bf16-split-3 tensor-core GEMM ----------------
// Block owns 32 gate-cols. Wh split slices (128 KB) resident in SMEM, frag layout.
// 16 warps: wid -> kg = wid&1 (K half), wq = wid>>1: wm = wq>>1 (32-row group),
// wn = wq&1 (16-col group). Per kb: 12 LDS.64 frag loads + 12 mma (3 split terms).
// h chunk-staged (4 kb, double buffered) from frag-native global via ldcg/STS128.
// Cross-kg reduce via SMEM; LSTM cell in kg=0 (gate pairs exchanged via shfl.xor 1).
__global__ __launch_bounds__(NT, 1) void lstm_persist(float* __restrict__ yout) {
    extern __shared__ float4 smf[];
    float4* Ws_f4 = smf;            // 8192 f4 = 128 KB, [term][kb][c][tg]
    float4* hs_f4 = smf + 8192;     // 4096 f4 = 64 KB: 2 bufs x [term][kbl(4)][row(128)][tg]

    const int tid  = threadIdx.x;
    const int wid  = tid >> 5;
    const int lane = tid & 31;
    const int kg   = wid & 1;
    const int wq   = wid >> 1;
    const int wm   = wq >> 1;       // 0..3
    const int wn   = wq & 1;        // 0..1
    const int m0   = wm * 32;
    const int g    = lane >> 2;     // 0..7
    const int tg   = lane & 3;      // 0..3
    const int n0   = blockIdx.x * 32;

    // --- one-time: Wh split slice -> SMEM (linear copy, frag layout preserved) ---
    {
        const float4* src = g_Whf + (size_t)blockIdx.x * 8192;
#pragma unroll
        for (int it = 0; it < 16; ++it) Ws_f4[tid + it * NT] = __ldcg(&src[tid + it * NT]);
    }
    __syncthreads();

    const char* Wsb = reinterpret_cast<const char*>(Ws_f4);

    float cs[2][2][2];              // cell state per (mt, nt, row-half), kg0 even-tg threads
#pragma unroll
    for (int a = 0; a < 2; ++a)
#pragma unroll
        for (int b = 0; b < 2; ++b) { cs[a][b][0] = 0.f; cs[a][b][1] = 0.f; }

    for (int t = 0; t < S_LEN; ++t) {
        const int pp_cur = t & 1;
        const int pp_nxt = (t + 1) & 1;

        // prefetch chunk 0 of h (2 terms x 4 kb x 128 rows x 4 tg = 2048 f4)
        float4 pf[4];
#pragma unroll
        for (int it = 0; it < 4; ++it) {
            int i = tid + it * NT;
            int term = i >> 10, off = i & 1023;
            pf[it] = __ldcg(&g_hf[((size_t)(pp_cur * 2 + term)) * 16384 + off]);
        }

        float acc[2][2][4];
#pragma unroll
        for (int a = 0; a < 2; ++a)
#pragma unroll
            for (int b = 0; b < 2; ++b)
#pragma unroll
                for (int q = 0; q < 4; ++q) acc[a][b][q] = 0.f;

        for (int c = 0; c < 16; ++c) {
            __syncthreads();        // previous chunk's consumers done with this buffer
            float4* buf = hs_f4 + (c & 1) * 2048;
#pragma unroll
            for (int it = 0; it < 4; ++it) buf[tid + it * NT] = pf[it];
            __syncthreads();
            if (c < 15) {
#pragma unroll
                for (int it = 0; it < 4; ++it) {
                    int i = tid + it * NT;
                    int term = i >> 10, off = i & 1023;
                    pf[it] = __ldcg(&g_hf[((size_t)(pp_cur * 2 + term)) * 16384 +
                                          (size_t)(c + 1) * 1024 + off]);
                }
            }

            const char* hsb = reinterpret_cast<const char*>(buf);
#pragma unroll
            for (int kk = 0; kk < 2; ++kk) {
                const int kbl = kg * 2 + kk;        // 0..3 within chunk
                const int kb  = c * 4 + kbl;        // global k-block

                // B fragments: [term][nt][2]
                unsigned bfr[2][2][2];
#pragma unroll
                for (int term = 0; term < 2; ++term)
#pragma unroll
                    for (int nt = 0; nt < 2; ++nt) {
                        u64 v = *reinterpret_cast<const u64*>(
                            Wsb + ((((size_t)(term * 64 + kb) * 32) +
                                    (wn * 16 + nt * 8 + g)) * 4 + tg) * 8);
                        bfr[term][nt][0] = (unsigned)v;
                        bfr[term][nt][1] = (unsigned)(v >> 32);
                    }

                // A fragments: [term][mt][4] = {lo.x, hi.x, lo.y, hi.y}
                unsigned afr[2][2][4];
#pragma unroll
                for (int term = 0; term < 2; ++term)
#pragma unroll
                    for (int mt = 0; mt < 2; ++mt) {
                        const char* pA = hsb + (size_t)term * 16384 +
                            (((size_t)(kbl * 128 + m0 + mt * 16 + g)) * 4 + tg) * 8;
                        u64 lo = *reinterpret_cast<const u64*>(pA);
                        u64 hi = *reinterpret_cast<const u64*>(pA + 256);  // +8 rows
                        afr[term][mt][0] = (unsigned)lo;
                        afr[term][mt][1] = (unsigned)hi;
                        afr[term][mt][2] = (unsigned)(lo >> 32);
                        afr[term][mt][3] = (unsigned)(hi >> 32);
                    }

#pragma unroll
                for (int mt = 0; mt < 2; ++mt)
#pragma unroll
                    for (int nt = 0; nt < 2; ++nt) {
                        MMA16816(acc[mt][nt], afr[0][mt], bfr[0][nt]);  // h1*W1
                        MMA16816(acc[mt][nt], afr[0][mt], bfr[1][nt]);  // h1*W2
                        MMA16816(acc[mt][nt], afr[1][mt], bfr[0][nt]);  // h2*W1
                    }
            }
        }

        // --- cross-kg reduce via SMEM (kg1 -> kg0); red uses buf0, last chunk used buf1 ---
        float4* red = hs_f4;
        if (kg == 1) {
#pragma unroll
            for (int q = 0; q < 4; ++q) {
                int mt = q >> 1, nt = q & 1;
                red[q * 256 + wq * 32 + lane] =
                    make_float4(acc[mt][nt][0], acc[mt][nt][1], acc[mt][nt][2], acc[mt][nt][3]);
            }
        }
        __syncthreads();
        if (kg == 0) {
#pragma unroll
            for (int q = 0; q < 4; ++q) {
                int mt = q >> 1, nt = q & 1;
                float4 r = red[q * 256 + wq * 32 + lane];
                acc[mt][nt][0] += r.x; acc[mt][nt][1] += r.y;
                acc[mt][nt][2] += r.z; acc[mt][nt][3] += r.w;
            }

            // --- LSTM cell epilogue ---
#pragma unroll
            for (int mt = 0; mt < 2; ++mt)
#pragma unroll
                for (int nt = 0; nt < 2; ++nt) {
                    const int r0 = m0 + mt * 16 + g;
                    const int r1 = r0 + 8;
                    const int ne = wn * 16 + nt * 8 + 2 * tg;
                    const float2 gxa = *reinterpret_cast<const float2*>(
                        &g_Gx[((size_t)r0 * S_LEN + t) * NGATE + n0 + ne]);
                    const float2 gxb = *reinterpret_cast<const float2*>(
                        &g_Gx[((size_t)r1 * S_LEN + t) * NGATE + n0 + ne]);
                    float p00 = acc[mt][nt][0] + gxa.x;
                    float p01 = acc[mt][nt][1] + gxa.y;
                    float p10 = acc[mt][nt][2] + gxb.x;
                    float p11 = acc[mt][nt][3] + gxb.y;
                    // exchange with partner lane (tg^1): it holds the other gate pair
                    u64 y0 = __shfl_xor_sync(0xffffffffu, pack2(p00, p01), 1);
                    u64 y1 = __shfl_xor_sync(0xffffffffu, pack2(p10, p11), 1);
                    if ((tg & 1) == 0) {
                        const int u = (n0 + ne) >> 2;   // hidden unit
                        float2 go0 = unpack2(y0);
                        float2 go1 = unpack2(y1);
                        // row r0
                        {
                            float fg = sigm_(p00), ig = sigm_(p01);
                            float gg = tanh_(go0.x), og = sigm_(go0.y);
                            cs[mt][nt][0] = cs[mt][nt][0] * fg + ig * gg;
                            float hv = tanh_(cs[mt][nt][0]) * og;
                            // split-store h into fragment-native global
                            __nv_bfloat16 h1 = __float2bfloat16(hv);
                            __nv_bfloat16 h2 = __float2bfloat16(hv - __bfloat162float(h1));
                            int kb_ = u >> 4, tgh, ph; jj_to_tgp(u & 15, tgh, ph);
                            __nv_bfloat16* hb = reinterpret_cast<__nv_bfloat16*>(g_hf);
                            size_t u1 = (((size_t)(pp_nxt * 2 + 0) * 64 + kb_) * 128 + r0) * 4 + tgh;
                            size_t u2 = (((size_t)(pp_nxt * 2 + 1) * 64 + kb_) * 128 + r0) * 4 + tgh;
                            st_cg_b16(&hb[u1 * 4 + ph], h1);
                            st_cg_b16(&hb[u2 * 4 + ph], h2);
                            yout[((size_t)r0 * S_LEN + t) * HID + u] = hv;
                        }
                        // row r1
                        {
                            float fg = sigm_(p10), ig = sigm_(p11);
                            float gg = tanh_(go1.x), og = sigm_(go1.y);
                            cs[mt][nt][1] = cs[mt][nt][1] * fg + ig * gg;
                            float hv = tanh_(cs[mt][nt][1]) * og;
                            __nv_bfloat16 h1 = __float2bfloat16(hv);
                            __nv_bfloat16 h2 = __float2bfloat16(hv - __bfloat162float(h1));
                            int kb_ = u >> 4, tgh, ph; jj_to_tgp(u & 15, tgh, ph);
                            __nv_bfloat16* hb = reinterpret_cast<__nv_bfloat16*>(g_hf);
                            size_t u1 = (((size_t)(pp_nxt * 2 + 0) * 64 + kb_) * 128 + r1) * 4 + tgh;
                            size_t u2 = (((size_t)(pp_nxt * 2 + 1) * 64 + kb_) * 128 + r1) * 4 + tgh;
                            st_cg_b16(&hb[u1 * 4 + ph], h1);
                            st_cg_b16(&hb[u2 * 4 + ph], h2);
                            yout[((size_t)r1 * S_LEN + t) * HID + u] = hv;
                        }
                    }
                }
        }

        // --- grid barrier (release/acquire), proven in R10 ---
        __syncthreads();   // epilogue stores ordered before tid0's release-arrive
        if (tid == 0) {
            unsigned old = atomAddRelease(&g_arrive, 1u);
            if (old == NB - 1) {
                asm volatile("st.global.relaxed.gpu.u32 [%0], %1;"
                             :: "l"(&g_arrive), "r"(0u) : "memory");
                atomAddRelease(&g_epoch, 1u);
            } else {
                unsigned target = (unsigned)t + 1u;
                while (ldAcquire(&g_epoch) < target) {}
            }
        }
        __syncthreads();   // propagate acquire to all threads
    }
}

// ---------------- launch ----------------
extern "C" void kernel_launch(void* const* d_in, const int* in_sizes, int n_in,
                              void* d_out, int out_size) {
    const float* x  = (const float*)d_in[0];
    const float* Wf = (const float*)d_in[1]; const float* bf = (const float*)d_in[2];
    const float* Wi = (const float*)d_in[3]; const float* bi = (const float*)d_in[4];
    const float* Wc = (const float*)d_in[5]; const float* bc = (const float*)d_in[6];
    const float* Wo = (const float*)d_in[7]; const float* bo = (const float*)d_in[8];
    float* out = (float*)d_out;

    init_state<<<(2 * 16384 + 255) / 256, 256>>>();
    repack<<<(NGATE * KDIM + 255) / 256, 256>>>(Wf, bf, Wi, bi, Wc, bc, Wo, bo);

    // Precompute Gx = bias + x @ Wx^T for all (b,t): M=32768, N=4096 (fp32)
    gemm_pre<128, 128, 16, 8, 8>
        <<<dim3(NGATE / 128, (BATCH * S_LEN) / 128), 256>>>(x);

    // Persistent recurrence: whole 256-step scan in one kernel, tensor-core inner GEMM
    const int smem_bytes = (8192 + 4096) * (int)sizeof(float4);  // 196608 B = 192 KB
    cudaFuncSetAttribute(lstm_persist, cudaFuncAttributeMaxDynamicSharedMemorySize, smem_bytes);
    lstm_persist<<<NB, NT, smem_bytes>>>(out);
}

// round 14
// speedup vs baseline: 2.0041x; 1.6451x over previous
#include <cuda_runtime.h>
#include <cuda_bf16.h>
#include <cstdint>
#include <math.h>

#define S_LEN 256
#define HID   1024
#define BATCH 128
#define NGATE 4096   // 4 * HID, gate-interleaved: n = j0*4 + gate (f,i,g,o)
#define KDIM  1024

#define NB 128       // persistent blocks (all co-resident; 1 per SM)
#define NT 512       // threads per persistent block (16 warps)

typedef unsigned long long u64;

// ---------------- device scratch (no allocs allowed) ----------------
__device__ float g_Wx[(size_t)NGATE * KDIM];          // x-part weights fp32, [n][k]
__device__ float g_bias[NGATE];
__device__ float g_Gx[(size_t)BATCH * S_LEN * NGATE]; // bias + x@Wx^T, row m=b*S+t

// Wh split (bf16 hi/lo) in mma-fragment-native layout:
//   [block(128)][term(2)][kb(64)][c(32)][tg(4)] 8B-units; unit holds bf16 at
//   k-offsets {2tg, 2tg+1, 2tg+8, 2tg+9} of k-block kb, gate-col c of the block.
__device__ float4 g_Whf[(size_t)128 * 2 * 64 * 32 * 2];   // 16 MB

// h split (bf16 hi/lo), ping-pong, fragment-native:
//   [pp(2)][term(2)][kb(64)][row(128)][tg(4)] 8B-units, same unit semantics (k = hidden j).
__device__ float4 g_hf[(size_t)2 * 2 * 64 * 128 * 2];     // 2 MB

__device__ unsigned g_arrive;
__device__ unsigned g_epoch;

// ---------------- helpers ----------------
__device__ __forceinline__ float2 unpack2(u64 v) {
    unsigned lo, hi;
    asm("mov.b64 {%0, %1}, %2;" : "=r"(lo), "=r"(hi) : "l"(v));
    return make_float2(__uint_as_float(lo), __uint_as_float(hi));
}
__device__ __forceinline__ u64 pack2(float lo, float hi) {
    u64 v; asm("mov.b64 %0, {%1, %2};" : "=l"(v) : "f"(lo), "f"(hi)); return v;
}
__device__ __forceinline__ u64 ffma2(u64 a, u64 b, u64 c) {
    u64 d; asm("fma.rn.f32x2 %0, %1, %2, %3;" : "=l"(d) : "l"(a), "l"(b), "l"(c)); return d;
}
__device__ __forceinline__ float sigm_(float x) {
    return __fdividef(1.0f, 1.0f + __expf(-x));
}
__device__ __forceinline__ float tanh_(float x) {
    return __fdividef(2.0f, 1.0f + __expf(-2.0f * x)) - 1.0f;
}
__device__ __forceinline__ unsigned atomAddRelease(unsigned* p, unsigned v) {
    unsigned o;
    asm volatile("atom.add.release.gpu.u32 %0, [%1], %2;"
                 : "=r"(o) : "l"(p), "r"(v) : "memory");
    return o;
}
__device__ __forceinline__ unsigned ldAcquire(unsigned* p) {
    unsigned o;
    asm volatile("ld.acquire.gpu.u32 %0, [%1];" : "=r"(o) : "l"(p) : "memory");
    return o;
}
__device__ __forceinline__ void st_cg_b16(void* p, __nv_bfloat16 v) {
    unsigned short u = *reinterpret_cast<unsigned short*>(&v);
    asm volatile("st.global.cg.u16 [%0], %1;" :: "l"(p), "h"(u) : "memory");
}
__device__ __forceinline__ void cpa16(void* smem, const void* gmem) {
    unsigned s = (unsigned)__cvta_generic_to_shared(smem);
    asm volatile("cp.async.cg.shared.global [%0], [%1], 16;" :: "r"(s), "l"(gmem));
}
#define CP_COMMIT() asm volatile("cp.async.commit_group;")
#define CP_WAIT(n)  asm volatile("cp.async.wait_group %0;" :: "n"(n))

// m16n8k16 row.col bf16 mma, fp32 accumulate (D==C in-place)
#define MMA16816(dd, aa, bb)                                                     \
    asm volatile(                                                                \
        "mma.sync.aligned.m16n8k16.row.col.f32.bf16.bf16.f32 "                   \
        "{%0,%1,%2,%3},{%4,%5,%6,%7},{%8,%9},{%0,%1,%2,%3};"                     \
        : "+f"((dd)[0]), "+f"((dd)[1]), "+f"((dd)[2]), "+f"((dd)[3])             \
        : "r"((aa)[0]), "r"((aa)[1]), "r"((aa)[2]), "r"((aa)[3]),                \
          "r"((bb)[0]), "r"((bb)[1]))

// (tg,p) position of hidden-index-within-16 jj inside an 8B fragment unit
__device__ __forceinline__ void jj_to_tgp(int jj, int& tg, int& p) {
    if (jj < 8) { tg = jj >> 1; p = jj & 1; }
    else        { tg = (jj >> 1) - 4; p = 2 + (jj & 1); }
}

// ---------------- init: zero h0 fragment buffer (pp=0) + barrier counters ----------------
__global__ void init_state() {
    int i = blockIdx.x * blockDim.x + threadIdx.x;
    if (i < 2 * 16384) g_hf[i] = make_float4(0.f, 0.f, 0.f, 0.f);  // pp=0: 2 terms x 16384 f4
    if (i == 0) { g_arrive = 0u; g_epoch = 0u; }
}

// ---------------- repack: x-weights fp32 [n][k] + bias + Wh bf16-split frag layout ----------
__global__ void repack(const float* __restrict__ Wf, const float* __restrict__ bf,
                       const float* __restrict__ Wi, const float* __restrict__ bi,
                       const float* __restrict__ Wc, const float* __restrict__ bc,
                       const float* __restrict__ Wo, const float* __restrict__ bo) {
    int idx = blockIdx.x * blockDim.x + threadIdx.x;
    if (idx >= NGATE * KDIM) return;
    int n = idx >> 10;           // n = j0*4 + gate
    int k = idx & 1023;
    int j0 = n >> 2;
    int g  = n & 3;
    const float* W = (g == 0) ? Wf : (g == 1) ? Wi : (g == 2) ? Wc : Wo;
    float vh = W[(size_t)j0 * 2048 + k];           // cols [0,H) act on h
    g_Wx[idx] = W[(size_t)j0 * 2048 + 1024 + k];   // cols [H,H+I) act on x
    if (k == 0) {
        const float* b = (g == 0) ? bf : (g == 1) ? bi : (g == 2) ? bc : bo;
        g_bias[n] = b[j0];
    }
    // bf16 split of the h-part weight into fragment layout
    __nv_bfloat16 w1 = __float2bfloat16(vh);
    __nv_bfloat16 w2 = __float2bfloat16(vh - __bfloat162float(w1));
    int blk = n >> 5;
    int c   = n & 31;
    int kb  = k >> 4;
    int tg, p; jj_to_tgp(k & 15, tg, p);
    __nv_bfloat16* base = reinterpret_cast<__nv_bfloat16*>(g_Whf);
    size_t u1 = ((((size_t)blk * 2 + 0) * 64 + kb) * 32 + c) * 4 + tg;
    size_t u2 = ((((size_t)blk * 2 + 1) * 64 + kb) * 32 + c) * 4 + tg;
    base[u1 * 4 + p] = w1;
    base[u2 * 4 + p] = w2;
}

// ---------------- precompute GEMM: Gx[m][n] = bias[n] + sum_k x[m][k]*Wx[n][k] ----------------
template<int BM, int BN, int BK, int TM, int TN>
__global__ __launch_bounds__(256) void gemm_pre(const float* __restrict__ A) {
    constexpr int TX = BN / TN;
    const int tid = threadIdx.x;
    const int tn  = tid % TX;
    const int tm  = tid / TX;
    const int n0  = blockIdx.x * BN;
    const int m0  = blockIdx.y * BM;

    __shared__ float As[BK][BM + 4];
    __shared__ float Bs[BK][BN + 4];

    u64 acc[TM][TN / 2];
#pragma unroll
    for (int i = 0; i < TM; ++i)
#pragma unroll
        for (int j = 0; j < TN / 2; ++j) acc[i][j] = 0ull;

    const float* Ab = A + (size_t)m0 * KDIM;
    const float* Wb = g_Wx + (size_t)n0 * KDIM;

    for (int k0 = 0; k0 < KDIM; k0 += BK) {
#pragma unroll
        for (int it = 0; it < (BM * BK / 4) / 256; ++it) {
            int id  = tid + it * 256;
            int row = id >> 2;
            int kq  = (id & 3) * 4;
            const float4 v = *reinterpret_cast<const float4*>(Ab + (size_t)row * KDIM + k0 + kq);
            As[kq + 0][row] = v.x; As[kq + 1][row] = v.y;
            As[kq + 2][row] = v.z; As[kq + 3][row] = v.w;
        }
#pragma unroll
        for (int it = 0; it < (BN * BK / 4) / 256; ++it) {
            int id  = tid + it * 256;
            int row = id >> 2;
            int kq  = (id & 3) * 4;
            const float4 v = *reinterpret_cast<const float4*>(Wb + (size_t)row * KDIM + k0 + kq);
            Bs[kq + 0][row] = v.x; Bs[kq + 1][row] = v.y;
            Bs[kq + 2][row] = v.z; Bs[kq + 3][row] = v.w;
        }
        __syncthreads();

#pragma unroll
        for (int kk = 0; kk < BK; ++kk) {
            float a[TM];
#pragma unroll
            for (int i = 0; i < TM / 4; ++i) {
                float4 v = *reinterpret_cast<const float4*>(&As[kk][tm * TM + i * 4]);
                a[i * 4 + 0] = v.x; a[i * 4 + 1] = v.y;
                a[i * 4 + 2] = v.z; a[i * 4 + 3] = v.w;
            }
            u64 bv[TN / 2];
#pragma unroll
            for (int j = 0; j < TN / 4; ++j) {
                const u64* p = reinterpret_cast<const u64*>(&Bs[kk][tn * TN + j * 4]);
                bv[j * 2 + 0] = p[0];
                bv[j * 2 + 1] = p[1];
            }
#pragma unroll
            for (int i = 0; i < TM; ++i) {
                u64 a2 = pack2(a[i], a[i]);
#pragma unroll
                for (int j = 0; j < TN / 2; ++j) acc[i][j] = ffma2(a2, bv[j], acc[i][j]);
            }
        }
        __syncthreads();
    }

#pragma unroll
    for (int i = 0; i < TM; ++i) {
        const int m = m0 + tm * TM + i;
        const int n = n0 + tn * TN;
        float* cp = g_Gx + (size_t)m * NGATE + n;
#pragma unroll
        for (int j = 0; j < TN / 4; ++j) {
            float4 bvv = *reinterpret_cast<const float4*>(g_bias + n + j * 4);
            float2 p0 = unpack2(acc[i][j * 2 + 0]);
            float2 p1 = unpack2(acc[i][j * 2 + 1]);
            float4 o;
            o.x = p0.x + bvv.x; o.y = p0.y + bvv.y;
            o.z = p1.x + bvv.z; o.w = p1.y + bvv.w;
            *reinterpret_cast<float4*>(cp + j * 4) = o;
        }
    }
}

// ---------------- persistent recurrence: bf16-split-3 mma + cp.async 3-stage pipeline -------
// Block owns 32 gate-cols. Wh split slices (128 KB) resident in SMEM, frag layout.
// 16 warps: kg = wid&1 (K half), wm = (wid>>1)>>1 (32-row group), wn = (wid>>1)&1.
// h chunks (4 kb = 32 KB) stream global->SMEM via cp.async with 3 buffers:
// per chunk: wait_group + ONE __syncthreads + issue chunk c+2 + compute chunk c.
__global__ __launch_bounds__(NT, 1) void lstm_persist(float* __restrict__ yout) {
    extern __shared__ float4 smf[];
    float4* Ws_f4 = smf;            // 8192 f4 = 128 KB, [term][kb][c][tg]
    float4* hs_f4 = smf + 8192;     // 3 x 2048 f4 = 96 KB pipeline buffers

    const int tid  = threadIdx.x;
    const int wid  = tid >> 5;
    const int lane = tid & 31;
    const int kg   = wid & 1;
    const int wq   = wid >> 1;
    const int wm   = wq >> 1;       // 0..3
    const int wn   = wq & 1;        // 0..1
    const int m0   = wm * 32;
    const int g    = lane >> 2;     // 0..7
    const int tg   = lane & 3;      // 0..3
    const int n0   = blockIdx.x * 32;

    // --- one-time: Wh split slice -> SMEM (linear copy, frag layout preserved) ---
    {
        const float4* src = g_Whf + (size_t)blockIdx.x * 8192;
#pragma unroll
        for (int it = 0; it < 16; ++it) Ws_f4[tid + it * NT] = __ldcg(&src[tid + it * NT]);
    }
    __syncthreads();

    const char* Wsb = reinterpret_cast<const char*>(Ws_f4);

    float cs[2][2][2];              // cell state per (mt, nt, row-half), kg0 even-tg threads
#pragma unroll
    for (int a = 0; a < 2; ++a)
#pragma unroll
        for (int b = 0; b < 2; ++b) { cs[a][b][0] = 0.f; cs[a][b][1] = 0.f; }

    for (int t = 0; t < S_LEN; ++t) {
        const int pp_cur = t & 1;
        const int pp_nxt = (t + 1) & 1;
        const float4* hsrc = g_hf + (size_t)(pp_cur * 2) * 16384;  // [term][...]

        // Gx epilogue operands: issue now, consumed ~a whole chunk-loop later
        float2 gxa[2][2], gxb[2][2];
        if (kg == 0) {
#pragma unroll
            for (int mt = 0; mt < 2; ++mt)
#pragma unroll
                for (int nt = 0; nt < 2; ++nt) {
                    const int r0 = m0 + mt * 16 + g;
                    const int ne = wn * 16 + nt * 8 + 2 * tg;
                    gxa[mt][nt] = __ldcg(reinterpret_cast<const float2*>(
                        &g_Gx[((size_t)r0 * S_LEN + t) * NGATE + n0 + ne]));
                    gxb[mt][nt] = __ldcg(reinterpret_cast<const float2*>(
                        &g_Gx[((size_t)(r0 + 8) * S_LEN + t) * NGATE + n0 + ne]));
                }
        }

        // pipeline prologue: chunks 0 and 1 in flight
#pragma unroll
        for (int c0 = 0; c0 < 2; ++c0) {
            float4* buf = hs_f4 + c0 * 2048;
#pragma unroll
            for (int it = 0; it < 4; ++it) {
                int i = tid + it * NT;
                int term = i >> 10, off = i & 1023;
                cpa16(&buf[i], &hsrc[(size_t)term * 16384 + (size_t)c0 * 1024 + off]);
            }
            CP_COMMIT();
        }

        float acc[2][2][4];
#pragma unroll
        for (int a = 0; a < 2; ++a)
#pragma unroll
            for (int b = 0; b < 2; ++b)
#pragma unroll
                for (int q = 0; q < 4; ++q) acc[a][b][q] = 0.f;

        for (int c = 0; c < 16; ++c) {
            if (c < 15) { CP_WAIT(1); } else { CP_WAIT(0); }
            __syncthreads();        // chunk c visible to all; buf (c+2)%3 free (chunk c-1 done)

            if (c + 2 < 16) {       // issue chunk c+2
                float4* nbuf = hs_f4 + ((c + 2) % 3) * 2048;
#pragma unroll
                for (int it = 0; it < 4; ++it) {
                    int i = tid + it * NT;
                    int term = i >> 10, off = i & 1023;
                    cpa16(&nbuf[i],
                          &hsrc[(size_t)term * 16384 + (size_t)(c + 2) * 1024 + off]);
                }
                CP_COMMIT();
            }

            const char* hsb = reinterpret_cast<const char*>(hs_f4 + (c % 3) * 2048);
#pragma unroll
            for (int kk = 0; kk < 2; ++kk) {
                const int kbl = kg * 2 + kk;        // 0..3 within chunk
                const int kb  = c * 4 + kbl;        // global k-block

                // B fragments: [term][nt][2]
                unsigned bfr[2][2][2];
#pragma unroll
                for (int term = 0; term < 2; ++term)
#pragma unroll
                    for (int nt = 0; nt < 2; ++nt) {
                        u64 v = *reinterpret_cast<const u64*>(
                            Wsb + ((((size_t)(term * 64 + kb) * 32) +
                                    (wn * 16 + nt * 8 + g)) * 4 + tg) * 8);
                        bfr[term][nt][0] = (unsigned)v;
                        bfr[term][nt][1] = (unsigned)(v >> 32);
                    }

                // A fragments: [term][mt][4] = {lo.x, hi.x, lo.y, hi.y}
                unsigned afr[2][2][4];
#pragma unroll
                for (int term = 0; term < 2; ++term)
#pragma unroll
                    for (int mt = 0; mt < 2; ++mt) {
                        const char* pA = hsb + (size_t)term * 16384 +
                            (((size_t)(kbl * 128 + m0 + mt * 16 + g)) * 4 + tg) * 8;
                        u64 lo = *reinterpret_cast<const u64*>(pA);
                        u64 hi = *reinterpret_cast<const u64*>(pA + 256);  // +8 rows
                        afr[term][mt][0] = (unsigned)lo;
                        afr[term][mt][1] = (unsigned)hi;
                        afr[term][mt][2] = (unsigned)(lo >> 32);
                        afr[term][mt][3] = (unsigned)(hi >> 32);
                    }

#pragma unroll
                for (int mt = 0; mt < 2; ++mt)
#pragma unroll
                    for (int nt = 0; nt < 2; ++nt) {
                        MMA16816(acc[mt][nt], afr[0][mt], bfr[0][nt]);  // h1*W1
                        MMA16816(acc[mt][nt], afr[0][mt], bfr[1][nt]);  // h1*W2
                        MMA16816(acc[mt][nt], afr[1][mt], bfr[0][nt]);  // h2*W1
                    }
            }
        }

        // all compute done reading hs buffers before reduce reuses buf 0
        __syncthreads();

        // --- cross-kg reduce via SMEM (kg1 -> kg0) ---
        float4* red = hs_f4;
        if (kg == 1) {
#pragma unroll
            for (int q = 0; q < 4; ++q) {
                int mt = q >> 1, nt = q & 1;
                red[q * 256 + wq * 32 + lane] =
                    make_float4(acc[mt][nt][0], acc[mt][nt][1], acc[mt][nt][2], acc[mt][nt][3]);
            }
        }
        __syncthreads();
        if (kg == 0) {
#pragma unroll
            for (int q = 0; q < 4; ++q) {
                int mt = q >> 1, nt = q & 1;
                float4 r = red[q * 256 + wq * 32 + lane];
                acc[mt][nt][0] += r.x; acc[mt][nt][1] += r.y;
                acc[mt][nt][2] += r.z; acc[mt][nt][3] += r.w;
            }

            // --- LSTM cell epilogue ---
#pragma unroll
            for (int mt = 0; mt < 2; ++mt)
#pragma unroll
                for (int nt = 0; nt < 2; ++nt) {
                    const int r0 = m0 + mt * 16 + g;
                    const int r1 = r0 + 8;
                    const int ne = wn * 16 + nt * 8 + 2 * tg;
                    float p00 = acc[mt][nt][0] + gxa[mt][nt].x;
                    float p01 = acc[mt][nt][1] + gxa[mt][nt].y;
                    float p10 = acc[mt][nt][2] + gxb[mt][nt].x;
                    float p11 = acc[mt][nt][3] + gxb[mt][nt].y;
                    // exchange with partner lane (tg^1): it holds the other gate pair
                    u64 y0 = __shfl_xor_sync(0xffffffffu, pack2(p00, p01), 1);
                    u64 y1 = __shfl_xor_sync(0xffffffffu, pack2(p10, p11), 1);
                    if ((tg & 1) == 0) {
                        const int u = (n0 + ne) >> 2;   // hidden unit
                        float2 go0 = unpack2(y0);
                        float2 go1 = unpack2(y1);
                        // row r0
                        {
                            float fg = sigm_(p00), ig = sigm_(p01);
                            float gg = tanh_(go0.x), og = sigm_(go0.y);
                            cs[mt][nt][0] = cs[mt][nt][0] * fg + ig * gg;
                            float hv = tanh_(cs[mt][nt][0]) * og;
                            __nv_bfloat16 h1 = __float2bfloat16(hv);
                            __nv_bfloat16 h2 = __float2bfloat16(hv - __bfloat162float(h1));
                            int kb_ = u >> 4, tgh, ph; jj_to_tgp(u & 15, tgh, ph);
                            __nv_bfloat16* hb = reinterpret_cast<__nv_bfloat16*>(g_hf);
                            size_t u1 = (((size_t)(pp_nxt * 2 + 0) * 64 + kb_) * 128 + r0) * 4 + tgh;
                            size_t u2 = (((size_t)(pp_nxt * 2 + 1) * 64 + kb_) * 128 + r0) * 4 + tgh;
                            st_cg_b16(&hb[u1 * 4 + ph], h1);
                            st_cg_b16(&hb[u2 * 4 + ph], h2);
                            yout[((size_t)r0 * S_LEN + t) * HID + u] = hv;
                        }
                        // row r1
                        {
                            float fg = sigm_(p10), ig = sigm_(p11);
                            float gg = tanh_(go1.x), og = sigm_(go1.y);
                            cs[mt][nt][1] = cs[mt][nt][1] * fg + ig * gg;
                            float hv = tanh_(cs[mt][nt][1]) * og;
                            __nv_bfloat16 h1 = __float2bfloat16(hv);
                            __nv_bfloat16 h2 = __float2bfloat16(hv - __bfloat162float(h1));
                            int kb_ = u >> 4, tgh, ph; jj_to_tgp(u & 15, tgh, ph);
                            __nv_bfloat16* hb = reinterpret_cast<__nv_bfloat16*>(g_hf);
                            size_t u1 = (((size_t)(pp_nxt * 2 + 0) * 64 + kb_) * 128 + r1) * 4 + tgh;
                            size_t u2 = (((size_t)(pp_nxt * 2 + 1) * 64 + kb_) * 128 + r1) * 4 + tgh;
                            st_cg_b16(&hb[u1 * 4 + ph], h1);
                            st_cg_b16(&hb[u2 * 4 + ph], h2);
                            yout[((size_t)r1 * S_LEN + t) * HID + u] = hv;
                        }
                    }
                }
        }

        // --- grid barrier (release/acquire), proven in R10/R12 ---
        __syncthreads();   // epilogue stores ordered before tid0's release-arrive
        if (tid == 0) {
            unsigned old = atomAddRelease(&g_arrive, 1u);
            if (old == NB - 1) {
                asm volatile("st.global.relaxed.gpu.u32 [%0], %1;"
                             :: "l"(&g_arrive), "r"(0u) : "memory");
                atomAddRelease(&g_epoch, 1u);
            } else {
                unsigned target = (unsigned)t + 1u;
                while (ldAcquire(&g_epoch) < target) {}
            }
        }
        __syncthreads();   // propagate acquire to all threads
    }
}

// ---------------- launch ----------------
extern "C" void kernel_launch(void* const* d_in, const int* in_sizes, int n_in,
                              void* d_out, int out_size) {
    const float* x  = (const float*)d_in[0];
    const float* Wf = (const float*)d_in[1]; const float* bf = (const float*)d_in[2];
    const float* Wi = (const float*)d_in[3]; const float* bi = (const float*)d_in[4];
    const float* Wc = (const float*)d_in[5]; const float* bc = (const float*)d_in[6];
    const float* Wo = (const float*)d_in[7]; const float* bo = (const float*)d_in[8];
    float* out = (float*)d_out;

    init_state<<<(2 * 16384 + 255) / 256, 256>>>();
    repack<<<(NGATE * KDIM + 255) / 256, 256>>>(Wf, bf, Wi, bi, Wc, bc, Wo, bo);

    // Precompute Gx = bias + x @ Wx^T for all (b,t): M=32768, N=4096 (fp32)
    gemm_pre<128, 128, 16, 8, 8>
        <<<dim3(NGATE / 128, (BATCH * S_LEN) / 128), 256>>>(x);

    // Persistent recurrence: whole 256-step scan, cp.async-pipelined h staging
    const int smem_bytes = (8192 + 3 * 2048) * (int)sizeof(float4);  // 229376 B = 224 KB
    cudaFuncSetAttribute(lstm_persist, cudaFuncAttributeMaxDynamicSharedMemorySize, smem_bytes);
    lstm_persist<<<NB, NT, smem_bytes>>>(out);
}

// round 15
// speedup vs baseline: 3.0476x; 1.5207x over previous
#include <cuda_runtime.h>
#include <cuda_bf16.h>
#include <cstdint>
#include <math.h>

#define S_LEN 256
#define HID   1024
#define BATCH 128
#define NGATE 4096   // 4 * HID, gate-interleaved: n = j0*4 + gate (f,i,g,o)
#define KDIM  1024

#define NB 128       // persistent blocks (all co-resident; 1 per SM)
#define NT 512       // threads per persistent block (16 warps)

typedef unsigned long long u64;

// ---------------- device scratch (no allocs allowed) ----------------
__device__ float g_bias[NGATE];
__device__ float g_Gx[(size_t)BATCH * S_LEN * NGATE]; // bias + x@Wx^T, row m=b*S+t

// Wh split (bf16 hi/lo) in mma-fragment-native layout:
//   [block(128)][term(2)][kb(64)][c(32)][tg(4)] 8B-units; unit holds bf16 at
//   k-offsets {2tg, 2tg+1, 2tg+8, 2tg+9} of k-block kb, gate-col c of the block.
__device__ float4 g_Whf[(size_t)128 * 2 * 64 * 32 * 2];   // 16 MB

// Wx split, fragment-native (flat over all 4096 gate cols):
//   [term(2)][kb(64)][col(4096)][tg(4)] 8B-units
__device__ float4 g_Wxf[(size_t)2 * 64 * 4096 * 2];       // 16 MB

// x split, fragment-native: [term(2)][kb(64)][row(32768)][tg(4)] 8B-units
__device__ float4 g_xf[(size_t)2 * 64 * 32768 * 2];       // 128 MB

// h split (bf16 hi/lo), ping-pong, fragment-native:
//   [pp(2)][term(2)][kb(64)][row(128)][tg(4)] 8B-units, same unit semantics (k = hidden j).
__device__ float4 g_hf[(size_t)2 * 2 * 64 * 128 * 2];     // 2 MB

__device__ unsigned g_arrive;
__device__ unsigned g_epoch;

// ---------------- helpers ----------------
__device__ __forceinline__ float2 unpack2(u64 v) {
    unsigned lo, hi;
    asm("mov.b64 {%0, %1}, %2;" : "=r"(lo), "=r"(hi) : "l"(v));
    return make_float2(__uint_as_float(lo), __uint_as_float(hi));
}
__device__ __forceinline__ u64 pack2(float lo, float hi) {
    u64 v; asm("mov.b64 %0, {%1, %2};" : "=l"(v) : "f"(lo), "f"(hi)); return v;
}
__device__ __forceinline__ float sigm_(float x) {
    return __fdividef(1.0f, 1.0f + __expf(-x));
}
__device__ __forceinline__ float tanh_(float x) {
    return __fdividef(2.0f, 1.0f + __expf(-2.0f * x)) - 1.0f;
}
__device__ __forceinline__ unsigned atomAddRelease(unsigned* p, unsigned v) {
    unsigned o;
    asm volatile("atom.add.release.gpu.u32 %0, [%1], %2;"
                 : "=r"(o) : "l"(p), "r"(v) : "memory");
    return o;
}
__device__ __forceinline__ unsigned ldAcquire(unsigned* p) {
    unsigned o;
    asm volatile("ld.acquire.gpu.u32 %0, [%1];" : "=r"(o) : "l"(p) : "memory");
    return o;
}
__device__ __forceinline__ void st_cg_b16(void* p, __nv_bfloat16 v) {
    unsigned short u = *reinterpret_cast<unsigned short*>(&v);
    asm volatile("st.global.cg.u16 [%0], %1;" :: "l"(p), "h"(u) : "memory");
}
__device__ __forceinline__ void cpa16(void* smem, const void* gmem) {
    unsigned s = (unsigned)__cvta_generic_to_shared(smem);
    asm volatile("cp.async.cg.shared.global [%0], [%1], 16;" :: "r"(s), "l"(gmem));
}
#define CP_COMMIT() asm volatile("cp.async.commit_group;")
#define CP_WAIT(n)  asm volatile("cp.async.wait_group %0;" :: "n"(n))

// m16n8k16 row.col bf16 mma, fp32 accumulate (D==C in-place)
#define MMA16816(dd, aa, bb)                                                     \
    asm volatile(                                                                \
        "mma.sync.aligned.m16n8k16.row.col.f32.bf16.bf16.f32 "                   \
        "{%0,%1,%2,%3},{%4,%5,%6,%7},{%8,%9},{%0,%1,%2,%3};"                     \
        : "+f"((dd)[0]), "+f"((dd)[1]), "+f"((dd)[2]), "+f"((dd)[3])             \
        : "r"((aa)[0]), "r"((aa)[1]), "r"((aa)[2]), "r"((aa)[3]),                \
          "r"((bb)[0]), "r"((bb)[1]))

// (tg,p) position of hidden-index-within-16 jj inside an 8B fragment unit
__device__ __forceinline__ void jj_to_tgp(int jj, int& tg, int& p) {
    if (jj < 8) { tg = jj >> 1; p = jj & 1; }
    else        { tg = (jj >> 1) - 4; p = 2 + (jj & 1); }
}

__device__ __forceinline__ u64 pack4bf(float a, float b, float c, float d) {
    __nv_bfloat16 h0 = __float2bfloat16(a), h1 = __float2bfloat16(b);
    __nv_bfloat16 h2 = __float2bfloat16(c), h3 = __float2bfloat16(d);
    u64 v = (u64)*reinterpret_cast<unsigned short*>(&h0)
          | ((u64)*reinterpret_cast<unsigned short*>(&h1) << 16)
          | ((u64)*reinterpret_cast<unsigned short*>(&h2) << 32)
          | ((u64)*reinterpret_cast<unsigned short*>(&h3) << 48);
    return v;
}
__device__ __forceinline__ float bfres(float x) {   // x - bf16(x)
    __nv_bfloat16 h = __float2bfloat16(x);
    return x - __bfloat162float(h);
}

// ---------------- init: zero h0 fragment buffer (pp=0) + barrier counters ----------------
__global__ void init_state() {
    int i = blockIdx.x * blockDim.x + threadIdx.x;
    if (i < 2 * 16384) g_hf[i] = make_float4(0.f, 0.f, 0.f, 0.f);  // pp=0: 2 terms x 16384 f4
    if (i == 0) { g_arrive = 0u; g_epoch = 0u; }
}

// ---------------- repack: Wh + Wx bf16-split fragment layouts + bias ----------------
__global__ void repack(const float* __restrict__ Wf, const float* __restrict__ bf,
                       const float* __restrict__ Wi, const float* __restrict__ bi,
                       const float* __restrict__ Wc, const float* __restrict__ bc,
                       const float* __restrict__ Wo, const float* __restrict__ bo) {
    int idx = blockIdx.x * blockDim.x + threadIdx.x;
    if (idx >= NGATE * KDIM) return;
    int n = idx >> 10;           // n = j0*4 + gate
    int k = idx & 1023;
    int j0 = n >> 2;
    int g  = n & 3;
    const float* W = (g == 0) ? Wf : (g == 1) ? Wi : (g == 2) ? Wc : Wo;
    float vh = W[(size_t)j0 * 2048 + k];           // cols [0,H) act on h
    float vx = W[(size_t)j0 * 2048 + 1024 + k];    // cols [H,H+I) act on x
    if (k == 0) {
        const float* b = (g == 0) ? bf : (g == 1) ? bi : (g == 2) ? bc : bo;
        g_bias[n] = b[j0];
    }
    int kb  = k >> 4;
    int tg, p; jj_to_tgp(k & 15, tg, p);

    // Wh split -> per-block fragment layout
    {
        __nv_bfloat16 w1 = __float2bfloat16(vh);
        __nv_bfloat16 w2 = __float2bfloat16(vh - __bfloat162float(w1));
        int blk = n >> 5;
        int c   = n & 31;
        __nv_bfloat16* base = reinterpret_cast<__nv_bfloat16*>(g_Whf);
        size_t u1 = ((((size_t)blk * 2 + 0) * 64 + kb) * 32 + c) * 4 + tg;
        size_t u2 = ((((size_t)blk * 2 + 1) * 64 + kb) * 32 + c) * 4 + tg;
        base[u1 * 4 + p] = w1;
        base[u2 * 4 + p] = w2;
    }
    // Wx split -> flat fragment layout over all 4096 cols
    {
        __nv_bfloat16 w1 = __float2bfloat16(vx);
        __nv_bfloat16 w2 = __float2bfloat16(vx - __bfloat162float(w1));
        __nv_bfloat16* base = reinterpret_cast<__nv_bfloat16*>(g_Wxf);
        size_t u1 = (((size_t)(0 * 64 + kb)) * 4096 + n) * 4 + tg;
        size_t u2 = (((size_t)(1 * 64 + kb)) * 4096 + n) * 4 + tg;
        base[u1 * 4 + p] = w1;
        base[u2 * 4 + p] = w2;
    }
}

// ---------------- xsplit: x fp32 -> (x1, x2) bf16 fragment layout ----------------
// One thread per 8B unit: reads 4 fp32 (k = kb*16 + {2tg,2tg+1,2tg+8,2tg+9}),
// writes one u64 per term. Unit-index ordering -> fully coalesced writes.
__global__ void xsplit(const float* __restrict__ x) {
    int i = blockIdx.x * blockDim.x + threadIdx.x;   // over 64*32768*4 units
    if (i >= 64 * 32768 * 4) return;
    int tg  = i & 3;
    int row = (i >> 2) & 32767;
    int kb  = i >> 17;
    const float* xr = x + (size_t)row * KDIM + kb * 16 + 2 * tg;
    float2 v0 = *reinterpret_cast<const float2*>(xr);      // k: 2tg, 2tg+1
    float2 v1 = *reinterpret_cast<const float2*>(xr + 8);  // k: 2tg+8, 2tg+9
    u64* xf = reinterpret_cast<u64*>(g_xf);
    size_t u1 = (((size_t)(0 * 64 + kb)) * 32768 + row) * 4 + tg;
    size_t u2 = (((size_t)(1 * 64 + kb)) * 32768 + row) * 4 + tg;
    xf[u1] = pack4bf(v0.x, v0.y, v1.x, v1.y);
    xf[u2] = pack4bf(bfres(v0.x), bfres(v0.y), bfres(v1.x), bfres(v1.y));
}

// ---------------- gemm_pre_mma: Gx = bias + x @ Wx^T, bf16 split-3 tensor cores --------
// BM=128, BN=128, 512 threads = 16 warps (wm 0..3 x wn 0..3, 32x32 warp tiles).
// K streamed in 16 chunks of 4 k-blocks via 3-buffer cp.async pipeline (192 KB smem).
__global__ __launch_bounds__(512, 1) void gemm_pre_mma() {
    extern __shared__ float4 smf[];
    // chunk buffer layout (4096 f4 each): A: [term(2)][kbl(4)][row(128)][j(2)] f4 (2048)
    //                                     B: [term(2)][kbl(4)][col(128)][j(2)] f4 (2048)
    const int tid  = threadIdx.x;
    const int wid  = tid >> 5;
    const int lane = tid & 31;
    const int wm   = wid >> 2;      // 0..3
    const int wn   = wid & 3;       // 0..3
    const int g    = lane >> 2;     // 0..7
    const int tg   = lane & 3;      // 0..3
    const int n0   = blockIdx.x * 128;
    const int m0g  = blockIdx.y * 128;

    const float4* Asrc = g_xf;      // ((term*64+kb)*32768 + row)*2 + j
    const float4* Bsrc = g_Wxf;     // ((term*64+kb)*4096  + col)*2 + j

    // pipeline prologue: chunks 0,1
#pragma unroll
    for (int c0 = 0; c0 < 2; ++c0) {
        float4* buf = smf + c0 * 4096;
#pragma unroll
        for (int it = 0; it < 8; ++it) {
            int i = tid + it * 512;
            if (i < 2048) {  // A
                int term = i >> 10, kbl = (i >> 8) & 3, row = (i >> 1) & 127, j = i & 1;
                cpa16(&buf[i],
                      &Asrc[((size_t)(term * 64 + c0 * 4 + kbl) * 32768 + m0g + row) * 2 + j]);
            } else {         // B
                int b = i - 2048;
                int term = b >> 10, kbl = (b >> 8) & 3, col = (b >> 1) & 127, j = b & 1;
                cpa16(&buf[i],
                      &Bsrc[((size_t)(term * 64 + c0 * 4 + kbl) * 4096 + n0 + col) * 2 + j]);
            }
        }
        CP_COMMIT();
    }

    float acc[2][4][4];
#pragma unroll
    for (int a = 0; a < 2; ++a)
#pragma unroll
        for (int b = 0; b < 4; ++b)
#pragma unroll
            for (int q = 0; q < 4; ++q) acc[a][b][q] = 0.f;

    for (int c = 0; c < 16; ++c) {
        if (c < 15) { CP_WAIT(1); } else { CP_WAIT(0); }
        __syncthreads();

        if (c + 2 < 16) {
            float4* nbuf = smf + ((c + 2) % 3) * 4096;
#pragma unroll
            for (int it = 0; it < 8; ++it) {
                int i = tid + it * 512;
                if (i < 2048) {
                    int term = i >> 10, kbl = (i >> 8) & 3, row = (i >> 1) & 127, j = i & 1;
                    cpa16(&nbuf[i],
                          &Asrc[((size_t)(term * 64 + (c + 2) * 4 + kbl) * 32768 + m0g + row) * 2 + j]);
                } else {
                    int b = i - 2048;
                    int term = b >> 10, kbl = (b >> 8) & 3, col = (b >> 1) & 127, j = b & 1;
                    cpa16(&nbuf[i],
                          &Bsrc[((size_t)(term * 64 + (c + 2) * 4 + kbl) * 4096 + n0 + col) * 2 + j]);
                }
            }
            CP_COMMIT();
        }

        const u64* bufu = reinterpret_cast<const u64*>(smf + (c % 3) * 4096);
#pragma unroll
        for (int kbl = 0; kbl < 4; ++kbl) {
            // B fragments: [term][nt][2]
            unsigned bfr[2][4][2];
#pragma unroll
            for (int term = 0; term < 2; ++term)
#pragma unroll
                for (int nt = 0; nt < 4; ++nt) {
                    int cb = wn * 32 + nt * 8 + g;
                    u64 v = bufu[4096 + ((size_t)(term * 4 + kbl) * 128 + cb) * 4 + tg];
                    bfr[term][nt][0] = (unsigned)v;
                    bfr[term][nt][1] = (unsigned)(v >> 32);
                }
            // A fragments: [term][mt][4]
            unsigned afr[2][2][4];
#pragma unroll
            for (int term = 0; term < 2; ++term)
#pragma unroll
                for (int mt = 0; mt < 2; ++mt) {
                    int ra = wm * 32 + mt * 16 + g;
                    u64 lo = bufu[((size_t)(term * 4 + kbl) * 128 + ra) * 4 + tg];
                    u64 hi = bufu[((size_t)(term * 4 + kbl) * 128 + ra + 8) * 4 + tg];
                    afr[term][mt][0] = (unsigned)lo;
                    afr[term][mt][1] = (unsigned)hi;
                    afr[term][mt][2] = (unsigned)(lo >> 32);
                    afr[term][mt][3] = (unsigned)(hi >> 32);
                }
#pragma unroll
            for (int mt = 0; mt < 2; ++mt)
#pragma unroll
                for (int nt = 0; nt < 4; ++nt) {
                    MMA16816(acc[mt][nt], afr[0][mt], bfr[0][nt]);  // x1*W1
                    MMA16816(acc[mt][nt], afr[0][mt], bfr[1][nt]);  // x1*W2
                    MMA16816(acc[mt][nt], afr[1][mt], bfr[0][nt]);  // x2*W1
                }
        }
    }

    // epilogue: add bias, store fp32 Gx
#pragma unroll
    for (int mt = 0; mt < 2; ++mt)
#pragma unroll
        for (int nt = 0; nt < 4; ++nt) {
            const int r0 = m0g + wm * 32 + mt * 16 + g;
            const int r1 = r0 + 8;
            const int nc = n0 + wn * 32 + nt * 8 + 2 * tg;
            float2 bv = *reinterpret_cast<const float2*>(g_bias + nc);
            float2 o0 = make_float2(acc[mt][nt][0] + bv.x, acc[mt][nt][1] + bv.y);
            float2 o1 = make_float2(acc[mt][nt][2] + bv.x, acc[mt][nt][3] + bv.y);
            *reinterpret_cast<float2*>(&g_Gx[(size_t)r0 * NGATE + nc]) = o0;
            *reinterpret_cast<float2*>(&g_Gx[(size_t)r1 * NGATE + nc]) = o1;
        }
}

// ---------------- persistent recurrence: bf16-split-3 mma + cp.async 3-stage pipeline -------
// (byte-identical to the R14 passing kernel)
__global__ __launch_bounds__(NT, 1) void lstm_persist(float* __restrict__ yout) {
    extern __shared__ float4 smf[];
    float4* Ws_f4 = smf;            // 8192 f4 = 128 KB, [term][kb][c][tg]
    float4* hs_f4 = smf + 8192;     // 3 x 2048 f4 = 96 KB pipeline buffers

    const int tid  = threadIdx.x;
    const int wid  = tid >> 5;
    const int lane = tid & 31;
    const int kg   = wid & 1;
    const int wq   = wid >> 1;
    const int wm   = wq >> 1;       // 0..3
    const int wn   = wq & 1;        // 0..1
    const int m0   = wm * 32;
    const int g    = lane >> 2;     // 0..7
    const int tg   = lane & 3;      // 0..3
    const int n0   = blockIdx.x * 32;

    // --- one-time: Wh split slice -> SMEM (linear copy, frag layout preserved) ---
    {
        const float4* src = g_Whf + (size_t)blockIdx.x * 8192;
#pragma unroll
        for (int it = 0; it < 16; ++it) Ws_f4[tid + it * NT] = __ldcg(&src[tid + it * NT]);
    }
    __syncthreads();

    const char* Wsb = reinterpret_cast<const char*>(Ws_f4);

    float cs[2][2][2];              // cell state per (mt, nt, row-half), kg0 even-tg threads
#pragma unroll
    for (int a = 0; a < 2; ++a)
#pragma unroll
        for (int b = 0; b < 2; ++b) { cs[a][b][0] = 0.f; cs[a][b][1] = 0.f; }

    for (int t = 0; t < S_LEN; ++t) {
        const int pp_cur = t & 1;
        const int pp_nxt = (t + 1) & 1;
        const float4* hsrc = g_hf + (size_t)(pp_cur * 2) * 16384;  // [term][...]

        // Gx epilogue operands: issue now, consumed ~a whole chunk-loop later
        float2 gxa[2][2], gxb[2][2];
        if (kg == 0) {
#pragma unroll
            for (int mt = 0; mt < 2; ++mt)
#pragma unroll
                for (int nt = 0; nt < 2; ++nt) {
                    const int r0 = m0 + mt * 16 + g;
                    const int ne = wn * 16 + nt * 8 + 2 * tg;
                    gxa[mt][nt] = __ldcg(reinterpret_cast<const float2*>(
                        &g_Gx[((size_t)r0 * S_LEN + t) * NGATE + n0 + ne]));
                    gxb[mt][nt] = __ldcg(reinterpret_cast<const float2*>(
                        &g_Gx[((size_t)(r0 + 8) * S_LEN + t) * NGATE + n0 + ne]));
                }
        }

        // pipeline prologue: chunks 0 and 1 in flight
#pragma unroll
        for (int c0 = 0; c0 < 2; ++c0) {
            float4* buf = hs_f4 + c0 * 2048;
#pragma unroll
            for (int it = 0; it < 4; ++it) {
                int i = tid + it * NT;
                int term = i >> 10, off = i & 1023;
                cpa16(&buf[i], &hsrc[(size_t)term * 16384 + (size_t)c0 * 1024 + off]);
            }
            CP_COMMIT();
        }

        float acc[2][2][4];
#pragma unroll
        for (int a = 0; a < 2; ++a)
#pragma unroll
            for (int b = 0; b < 2; ++b)
#pragma unroll
                for (int q = 0; q < 4; ++q) acc[a][b][q] = 0.f;

        for (int c = 0; c < 16; ++c) {
            if (c < 15) { CP_WAIT(1); } else { CP_WAIT(0); }
            __syncthreads();        // chunk c visible to all; buf (c+2)%3 free (chunk c-1 done)

            if (c + 2 < 16) {       // issue chunk c+2
                float4* nbuf = hs_f4 + ((c + 2) % 3) * 2048;
#pragma unroll
                for (int it = 0; it < 4; ++it) {
                    int i = tid + it * NT;
                    int term = i >> 10, off = i & 1023;
                    cpa16(&nbuf[i],
                          &hsrc[(size_t)term * 16384 + (size_t)(c + 2) * 1024 + off]);
                }
                CP_COMMIT();
            }

            const char* hsb = reinterpret_cast<const char*>(hs_f4 + (c % 3) * 2048);
#pragma unroll
            for (int kk = 0; kk < 2; ++kk) {
                const int kbl = kg * 2 + kk;        // 0..3 within chunk
                const int kb  = c * 4 + kbl;        // global k-block

                // B fragments: [term][nt][2]
                unsigned bfr[2][2][2];
#pragma unroll
                for (int term = 0; term < 2; ++term)
#pragma unroll
                    for (int nt = 0; nt < 2; ++nt) {
                        u64 v = *reinterpret_cast<const u64*>(
                            Wsb + ((((size_t)(term * 64 + kb) * 32) +
                                    (wn * 16 + nt * 8 + g)) * 4 + tg) * 8);
                        bfr[term][nt][0] = (unsigned)v;
                        bfr[term][nt][1] = (unsigned)(v >> 32);
                    }

                // A fragments: [term][mt][4] = {lo.x, hi.x, lo.y, hi.y}
                unsigned afr[2][2][4];
#pragma unroll
                for (int term = 0; term < 2; ++term)
#pragma unroll
                    for (int mt = 0; mt < 2; ++mt) {
                        const char* pA = hsb + (size_t)term * 16384 +
                            (((size_t)(kbl * 128 + m0 + mt * 16 + g)) * 4 + tg) * 8;
                        u64 lo = *reinterpret_cast<const u64*>(pA);
                        u64 hi = *reinterpret_cast<const u64*>(pA + 256);  // +8 rows
                        afr[term][mt][0] = (unsigned)lo;
                        afr[term][mt][1] = (unsigned)hi;
                        afr[term][mt][2] = (unsigned)(lo >> 32);
                        afr[term][mt][3] = (unsigned)(hi >> 32);
                    }

#pragma unroll
                for (int mt = 0; mt < 2; ++mt)
#pragma unroll
                    for (int nt = 0; nt < 2; ++nt) {
                        MMA16816(acc[mt][nt], afr[0][mt], bfr[0][nt]);  // h1*W1
                        MMA16816(acc[mt][nt], afr[0][mt], bfr[1][nt]);  // h1*W2
                        MMA16816(acc[mt][nt], afr[1][mt], bfr[0][nt]);  // h2*W1
                    }
            }
        }

        // all compute done reading hs buffers before reduce reuses buf 0
        __syncthreads();

        // --- cross-kg reduce via SMEM (kg1 -> kg0) ---
        float4* red = hs_f4;
        if (kg == 1) {
#pragma unroll
            for (int q = 0; q < 4; ++q) {
                int mt = q >> 1, nt = q & 1;
                red[q * 256 + wq * 32 + lane] =
                    make_float4(acc[mt][nt][0], acc[mt][nt][1], acc[mt][nt][2], acc[mt][nt][3]);
            }
        }
        __syncthreads();
        if (kg == 0) {
#pragma unroll
            for (int q = 0; q < 4; ++q) {
                int mt = q >> 1, nt = q & 1;
                float4 r = red[q * 256 + wq * 32 + lane];
                acc[mt][nt][0] += r.x; acc[mt][nt][1] += r.y;
                acc[mt][nt][2] += r.z; acc[mt][nt][3] += r.w;
            }

            // --- LSTM cell epilogue ---
#pragma unroll
            for (int mt = 0; mt < 2; ++mt)
#pragma unroll
                for (int nt = 0; nt < 2; ++nt) {
                    const int r0 = m0 + mt * 16 + g;
                    const int r1 = r0 + 8;
                    const int ne = wn * 16 + nt * 8 + 2 * tg;
                    float p00 = acc[mt][nt][0] + gxa[mt][nt].x;
                    float p01 = acc[mt][nt][1] + gxa[mt][nt].y;
                    float p10 = acc[mt][nt][2] + gxb[mt][nt].x;
                    float p11 = acc[mt][nt][3] + gxb[mt][nt].y;
                    // exchange with partner lane (tg^1): it holds the other gate pair
                    u64 y0 = __shfl_xor_sync(0xffffffffu, pack2(p00, p01), 1);
                    u64 y1 = __shfl_xor_sync(0xffffffffu, pack2(p10, p11), 1);
                    if ((tg & 1) == 0) {
                        const int u = (n0 + ne) >> 2;   // hidden unit
                        float2 go0 = unpack2(y0);
                        float2 go1 = unpack2(y1);
                        // row r0
                        {
                            float fg = sigm_(p00), ig = sigm_(p01);
                            float gg = tanh_(go0.x), og = sigm_(go0.y);
                            cs[mt][nt][0] = cs[mt][nt][0] * fg + ig * gg;
                            float hv = tanh_(cs[mt][nt][0]) * og;
                            __nv_bfloat16 h1 = __float2bfloat16(hv);
                            __nv_bfloat16 h2 = __float2bfloat16(hv - __bfloat162float(h1));
                            int kb_ = u >> 4, tgh, ph; jj_to_tgp(u & 15, tgh, ph);
                            __nv_bfloat16* hb = reinterpret_cast<__nv_bfloat16*>(g_hf);
                            size_t u1 = (((size_t)(pp_nxt * 2 + 0) * 64 + kb_) * 128 + r0) * 4 + tgh;
                            size_t u2 = (((size_t)(pp_nxt * 2 + 1) * 64 + kb_) * 128 + r0) * 4 + tgh;
                            st_cg_b16(&hb[u1 * 4 + ph], h1);
                            st_cg_b16(&hb[u2 * 4 + ph], h2);
                            yout[((size_t)r0 * S_LEN + t) * HID + u] = hv;
                        }
                        // row r1
                        {
                            float fg = sigm_(p10), ig = sigm_(p11);
                            float gg = tanh_(go1.x), og = sigm_(go1.y);
                            cs[mt][nt][1] = cs[mt][nt][1] * fg + ig * gg;
                            float hv = tanh_(cs[mt][nt][1]) * og;
                            __nv_bfloat16 h1 = __float2bfloat16(hv);
                            __nv_bfloat16 h2 = __float2bfloat16(hv - __bfloat162float(h1));
                            int kb_ = u >> 4, tgh, ph; jj_to_tgp(u & 15, tgh, ph);
                            __nv_bfloat16* hb = reinterpret_cast<__nv_bfloat16*>(g_hf);
                            size_t u1 = (((size_t)(pp_nxt * 2 + 0) * 64 + kb_) * 128 + r1) * 4 + tgh;
                            size_t u2 = (((size_t)(pp_nxt * 2 + 1) * 64 + kb_) * 128 + r1) * 4 + tgh;
                            st_cg_b16(&hb[u1 * 4 + ph], h1);
                            st_cg_b16(&hb[u2 * 4 + ph], h2);
                            yout[((size_t)r1 * S_LEN + t) * HID + u] = hv;
                        }
                    }
                }
        }

        // --- grid barrier (release/acquire), proven in R10/R12/R14 ---
        __syncthreads();   // epilogue stores ordered before tid0's release-arrive
        if (tid == 0) {
            unsigned old = atomAddRelease(&g_arrive, 1u);
            if (old == NB - 1) {
                asm volatile("st.global.relaxed.gpu.u32 [%0], %1;"
                             :: "l"(&g_arrive), "r"(0u) : "memory");
                atomAddRelease(&g_epoch, 1u);
            } else {
                unsigned target = (unsigned)t + 1u;
                while (ldAcquire(&g_epoch) < target) {}
            }
        }
        __syncthreads();   // propagate acquire to all threads
    }
}

// ---------------- launch ----------------
extern "C" void kernel_launch(void* const* d_in, const int* in_sizes, int n_in,
                              void* d_out, int out_size) {
    const float* x  = (const float*)d_in[0];
    const float* Wf = (const float*)d_in[1]; const float* bf = (const float*)d_in[2];
    const float* Wi = (const float*)d_in[3]; const float* bi = (const float*)d_in[4];
    const float* Wc = (const float*)d_in[5]; const float* bc = (const float*)d_in[6];
    const float* Wo = (const float*)d_in[7]; const float* bo = (const float*)d_in[8];
    float* out = (float*)d_out;

    init_state<<<(2 * 16384 + 255) / 256, 256>>>();
    repack<<<(NGATE * KDIM + 255) / 256, 256>>>(Wf, bf, Wi, bi, Wc, bc, Wo, bo);
    xsplit<<<(64 * 32768 * 4 + 255) / 256, 256>>>(x);

    // Precompute Gx = bias + x @ Wx^T via bf16 split-3 tensor cores
    const int pre_smem = 3 * 4096 * (int)sizeof(float4);   // 196608 B = 192 KB
    cudaFuncSetAttribute(gemm_pre_mma, cudaFuncAttributeMaxDynamicSharedMemorySize, pre_smem);
    gemm_pre_mma<<<dim3(NGATE / 128, (BATCH * S_LEN) / 128), 512, pre_smem>>>();

    // Persistent recurrence: whole 256-step scan, cp.async-pipelined h staging
    const int smem_bytes = (8192 + 3 * 2048) * (int)sizeof(float4);  // 229376 B = 224 KB
    cudaFuncSetAttribute(lstm_persist, cudaFuncAttributeMaxDynamicSharedMemorySize, smem_bytes);
    lstm_persist<<<NB, NT, smem_bytes>>>(out);
}

// round 16
// speedup vs baseline: 3.1909x; 1.0470x over previous
#include <cuda_runtime.h>
#include <cuda_bf16.h>
#include <cstdint>
#include <math.h>

#define S_LEN 256
#define HID   1024
#define BATCH 128
#define NGATE 4096   // 4 * HID, gate-interleaved: n = j0*4 + gate (f,i,g,o)
#define KDIM  1024

#define NB 128       // persistent blocks (all co-resident; 1 per SM)
#define NT 512       // threads per persistent block (16 warps)

typedef unsigned long long u64;

// ---------------- device scratch (no allocs allowed) ----------------
__device__ float g_bias[NGATE];
__device__ float g_Gx[(size_t)BATCH * S_LEN * NGATE]; // bias + x@Wx^T, row m=b*S+t

// Wh split (bf16 hi/lo) in mma-fragment-native layout:
//   [block(128)][term(2)][kb(64)][c(32)][tg(4)] 8B-units; unit holds bf16 at
//   k-offsets {2tg, 2tg+1, 2tg+8, 2tg+9} of k-block kb, gate-col c of the block.
__device__ float4 g_Whf[(size_t)128 * 2 * 64 * 32 * 2];   // 16 MB

// Wx split, fragment-native (flat over all 4096 gate cols):
//   [term(2)][kb(64)][col(4096)][tg(4)] 8B-units
__device__ float4 g_Wxf[(size_t)2 * 64 * 4096 * 2];       // 16 MB

// x split, fragment-native: [term(2)][kb(64)][row(32768)][tg(4)] 8B-units
__device__ float4 g_xf[(size_t)2 * 64 * 32768 * 2];       // 128 MB

// h split (bf16 hi/lo), ping-pong, fragment-native:
//   [pp(2)][term(2)][kb(64)][row(128)][tg(4)] 8B-units, same unit semantics (k = hidden j).
__device__ float4 g_hf[(size_t)2 * 2 * 64 * 128 * 2];     // 2 MB

__device__ unsigned g_arrive;
__device__ unsigned g_epoch;

// ---------------- helpers ----------------
__device__ __forceinline__ float2 unpack2(u64 v) {
    unsigned lo, hi;
    asm("mov.b64 {%0, %1}, %2;" : "=r"(lo), "=r"(hi) : "l"(v));
    return make_float2(__uint_as_float(lo), __uint_as_float(hi));
}
__device__ __forceinline__ u64 pack2(float lo, float hi) {
    u64 v; asm("mov.b64 %0, {%1, %2};" : "=l"(v) : "f"(lo), "f"(hi)); return v;
}
__device__ __forceinline__ float sigm_(float x) {
    return __fdividef(1.0f, 1.0f + __expf(-x));
}
__device__ __forceinline__ float tanh_(float x) {
    return __fdividef(2.0f, 1.0f + __expf(-2.0f * x)) - 1.0f;
}
__device__ __forceinline__ unsigned atomAddRelease(unsigned* p, unsigned v) {
    unsigned o;
    asm volatile("atom.add.release.gpu.u32 %0, [%1], %2;"
                 : "=r"(o) : "l"(p), "r"(v) : "memory");
    return o;
}
__device__ __forceinline__ unsigned ldAcquire(unsigned* p) {
    unsigned o;
    asm volatile("ld.acquire.gpu.u32 %0, [%1];" : "=r"(o) : "l"(p) : "memory");
    return o;
}
__device__ __forceinline__ void st_cg_b16(void* p, __nv_bfloat16 v) {
    unsigned short u = *reinterpret_cast<unsigned short*>(&v);
    asm volatile("st.global.cg.u16 [%0], %1;" :: "l"(p), "h"(u) : "memory");
}
__device__ __forceinline__ void cpa16(void* smem, const void* gmem) {
    unsigned s = (unsigned)__cvta_generic_to_shared(smem);
    asm volatile("cp.async.cg.shared.global [%0], [%1], 16;" :: "r"(s), "l"(gmem));
}
#define CP_COMMIT() asm volatile("cp.async.commit_group;")
#define CP_WAIT(n)  asm volatile("cp.async.wait_group %0;" :: "n"(n))

// ---- bulk async copy (UBLKCP) + mbarrier primitives ----
__device__ __forceinline__ void cpbulk(void* smem, const void* gmem, unsigned bytes,
                                       void* mbar_smem) {
    unsigned s  = (unsigned)__cvta_generic_to_shared(smem);
    unsigned mb = (unsigned)__cvta_generic_to_shared(mbar_smem);
    asm volatile(
        "cp.async.bulk.shared::cta.global.mbarrier::complete_tx::bytes [%0], [%1], %2, [%3];"
        :: "r"(s), "l"(gmem), "r"(bytes), "r"(mb) : "memory");
}
__device__ __forceinline__ void mbar_init(void* mbar_smem, unsigned count) {
    unsigned mb = (unsigned)__cvta_generic_to_shared(mbar_smem);
    asm volatile("mbarrier.init.shared.b64 [%0], %1;" :: "r"(mb), "r"(count) : "memory");
}
__device__ __forceinline__ void mbar_expect_tx(void* mbar_smem, unsigned bytes) {
    unsigned mb = (unsigned)__cvta_generic_to_shared(mbar_smem);
    asm volatile("mbarrier.arrive.expect_tx.shared.b64 _, [%0], %1;"
                 :: "r"(mb), "r"(bytes) : "memory");
}
__device__ __forceinline__ void mbar_wait(void* mbar_smem, unsigned parity) {
    unsigned mb = (unsigned)__cvta_generic_to_shared(mbar_smem);
    unsigned done;
    asm volatile(
        "{\n\t.reg .pred p;\n\t"
        "mbarrier.try_wait.parity.acquire.cta.shared::cta.b64 p, [%1], %2;\n\t"
        "selp.b32 %0, 1, 0, p;\n\t}"
        : "=r"(done) : "r"(mb), "r"(parity) : "memory");
    if (!done) {
        asm volatile(
            "{\n\t.reg .pred P1;\n\t"
            "WAIT_LOOP_%=:\n\t"
            "mbarrier.try_wait.parity.acquire.cta.shared::cta.b64 P1, [%0], %1, 0x989680;\n\t"
            "@P1 bra.uni WAIT_DONE_%=;\n\t"
            "bra.uni WAIT_LOOP_%=;\n\t"
            "WAIT_DONE_%=:\n\t}"
            :: "r"(mb), "r"(parity) : "memory");
    }
}

// m16n8k16 row.col bf16 mma, fp32 accumulate (D==C in-place)
#define MMA16816(dd, aa, bb)                                                     \
    asm volatile(                                                                \
        "mma.sync.aligned.m16n8k16.row.col.f32.bf16.bf16.f32 "                   \
        "{%0,%1,%2,%3},{%4,%5,%6,%7},{%8,%9},{%0,%1,%2,%3};"                     \
        : "+f"((dd)[0]), "+f"((dd)[1]), "+f"((dd)[2]), "+f"((dd)[3])             \
        : "r"((aa)[0]), "r"((aa)[1]), "r"((aa)[2]), "r"((aa)[3]),                \
          "r"((bb)[0]), "r"((bb)[1]))

// (tg,p) position of hidden-index-within-16 jj inside an 8B fragment unit
__device__ __forceinline__ void jj_to_tgp(int jj, int& tg, int& p) {
    if (jj < 8) { tg = jj >> 1; p = jj & 1; }
    else        { tg = (jj >> 1) - 4; p = 2 + (jj & 1); }
}

__device__ __forceinline__ u64 pack4bf(float a, float b, float c, float d) {
    __nv_bfloat16 h0 = __float2bfloat16(a), h1 = __float2bfloat16(b);
    __nv_bfloat16 h2 = __float2bfloat16(c), h3 = __float2bfloat16(d);
    u64 v = (u64)*reinterpret_cast<unsigned short*>(&h0)
          | ((u64)*reinterpret_cast<unsigned short*>(&h1) << 16)
          | ((u64)*reinterpret_cast<unsigned short*>(&h2) << 32)
          | ((u64)*reinterpret_cast<unsigned short*>(&h3) << 48);
    return v;
}
__device__ __forceinline__ float bfres(float x) {   // x - bf16(x)
    __nv_bfloat16 h = __float2bfloat16(x);
    return x - __bfloat162float(h);
}

// ---------------- init: zero h0 fragment buffer (pp=0) + barrier counters ----------------
__global__ void init_state() {
    int i = blockIdx.x * blockDim.x + threadIdx.x;
    if (i < 2 * 16384) g_hf[i] = make_float4(0.f, 0.f, 0.f, 0.f);  // pp=0: 2 terms x 16384 f4
    if (i == 0) { g_arrive = 0u; g_epoch = 0u; }
}

// ---------------- repack: Wh + Wx bf16-split fragment layouts + bias ----------------
__global__ void repack(const float* __restrict__ Wf, const float* __restrict__ bf,
                       const float* __restrict__ Wi, const float* __restrict__ bi,
                       const float* __restrict__ Wc, const float* __restrict__ bc,
                       const float* __restrict__ Wo, const float* __restrict__ bo) {
    int idx = blockIdx.x * blockDim.x + threadIdx.x;
    if (idx >= NGATE * KDIM) return;
    int n = idx >> 10;           // n = j0*4 + gate
    int k = idx & 1023;
    int j0 = n >> 2;
    int g  = n & 3;
    const float* W = (g == 0) ? Wf : (g == 1) ? Wi : (g == 2) ? Wc : Wo;
    float vh = W[(size_t)j0 * 2048 + k];           // cols [0,H) act on h
    float vx = W[(size_t)j0 * 2048 + 1024 + k];    // cols [H,H+I) act on x
    if (k == 0) {
        const float* b = (g == 0) ? bf : (g == 1) ? bi : (g == 2) ? bc : bo;
        g_bias[n] = b[j0];
    }
    int kb  = k >> 4;
    int tg, p; jj_to_tgp(k & 15, tg, p);

    // Wh split -> per-block fragment layout
    {
        __nv_bfloat16 w1 = __float2bfloat16(vh);
        __nv_bfloat16 w2 = __float2bfloat16(vh - __bfloat162float(w1));
        int blk = n >> 5;
        int c   = n & 31;
        __nv_bfloat16* base = reinterpret_cast<__nv_bfloat16*>(g_Whf);
        size_t u1 = ((((size_t)blk * 2 + 0) * 64 + kb) * 32 + c) * 4 + tg;
        size_t u2 = ((((size_t)blk * 2 + 1) * 64 + kb) * 32 + c) * 4 + tg;
        base[u1 * 4 + p] = w1;
        base[u2 * 4 + p] = w2;
    }
    // Wx split -> flat fragment layout over all 4096 cols
    {
        __nv_bfloat16 w1 = __float2bfloat16(vx);
        __nv_bfloat16 w2 = __float2bfloat16(vx - __bfloat162float(w1));
        __nv_bfloat16* base = reinterpret_cast<__nv_bfloat16*>(g_Wxf);
        size_t u1 = (((size_t)(0 * 64 + kb)) * 4096 + n) * 4 + tg;
        size_t u2 = (((size_t)(1 * 64 + kb)) * 4096 + n) * 4 + tg;
        base[u1 * 4 + p] = w1;
        base[u2 * 4 + p] = w2;
    }
}

// ---------------- xsplit: x fp32 -> (x1, x2) bf16 fragment layout ----------------
__global__ void xsplit(const float* __restrict__ x) {
    int i = blockIdx.x * blockDim.x + threadIdx.x;   // over 64*32768*4 units
    if (i >= 64 * 32768 * 4) return;
    int tg  = i & 3;
    int row = (i >> 2) & 32767;
    int kb  = i >> 17;
    const float* xr = x + (size_t)row * KDIM + kb * 16 + 2 * tg;
    float2 v0 = *reinterpret_cast<const float2*>(xr);      // k: 2tg, 2tg+1
    float2 v1 = *reinterpret_cast<const float2*>(xr + 8);  // k: 2tg+8, 2tg+9
    u64* xf = reinterpret_cast<u64*>(g_xf);
    size_t u1 = (((size_t)(0 * 64 + kb)) * 32768 + row) * 4 + tg;
    size_t u2 = (((size_t)(1 * 64 + kb)) * 32768 + row) * 4 + tg;
    xf[u1] = pack4bf(v0.x, v0.y, v1.x, v1.y);
    xf[u2] = pack4bf(bfres(v0.x), bfres(v0.y), bfres(v1.x), bfres(v1.y));
}

// ---------------- gemm_pre_mma: Gx = bias + x @ Wx^T, bf16 split-3 tensor cores --------
// (byte-identical to the R15 passing kernel)
__global__ __launch_bounds__(512, 1) void gemm_pre_mma() {
    extern __shared__ float4 smf[];
    const int tid  = threadIdx.x;
    const int wid  = tid >> 5;
    const int lane = tid & 31;
    const int wm   = wid >> 2;      // 0..3
    const int wn   = wid & 3;       // 0..3
    const int g    = lane >> 2;     // 0..7
    const int tg   = lane & 3;      // 0..3
    const int n0   = blockIdx.x * 128;
    const int m0g  = blockIdx.y * 128;

    const float4* Asrc = g_xf;      // ((term*64+kb)*32768 + row)*2 + j
    const float4* Bsrc = g_Wxf;     // ((term*64+kb)*4096  + col)*2 + j

#pragma unroll
    for (int c0 = 0; c0 < 2; ++c0) {
        float4* buf = smf + c0 * 4096;
#pragma unroll
        for (int it = 0; it < 8; ++it) {
            int i = tid + it * 512;
            if (i < 2048) {  // A
                int term = i >> 10, kbl = (i >> 8) & 3, row = (i >> 1) & 127, j = i & 1;
                cpa16(&buf[i],
                      &Asrc[((size_t)(term * 64 + c0 * 4 + kbl) * 32768 + m0g + row) * 2 + j]);
            } else {         // B
                int b = i - 2048;
                int term = b >> 10, kbl = (b >> 8) & 3, col = (b >> 1) & 127, j = b & 1;
                cpa16(&buf[i],
                      &Bsrc[((size_t)(term * 64 + c0 * 4 + kbl) * 4096 + n0 + col) * 2 + j]);
            }
        }
        CP_COMMIT();
    }

    float acc[2][4][4];
#pragma unroll
    for (int a = 0; a < 2; ++a)
#pragma unroll
        for (int b = 0; b < 4; ++b)
#pragma unroll
            for (int q = 0; q < 4; ++q) acc[a][b][q] = 0.f;

    for (int c = 0; c < 16; ++c) {
        if (c < 15) { CP_WAIT(1); } else { CP_WAIT(0); }
        __syncthreads();

        if (c + 2 < 16) {
            float4* nbuf = smf + ((c + 2) % 3) * 4096;
#pragma unroll
            for (int it = 0; it < 8; ++it) {
                int i = tid + it * 512;
                if (i < 2048) {
                    int term = i >> 10, kbl = (i >> 8) & 3, row = (i >> 1) & 127, j = i & 1;
                    cpa16(&nbuf[i],
                          &Asrc[((size_t)(term * 64 + (c + 2) * 4 + kbl) * 32768 + m0g + row) * 2 + j]);
                } else {
                    int b = i - 2048;
                    int term = b >> 10, kbl = (b >> 8) & 3, col = (b >> 1) & 127, j = b & 1;
                    cpa16(&nbuf[i],
                          &Bsrc[((size_t)(term * 64 + (c + 2) * 4 + kbl) * 4096 + n0 + col) * 2 + j]);
                }
            }
            CP_COMMIT();
        }

        const u64* bufu = reinterpret_cast<const u64*>(smf + (c % 3) * 4096);
#pragma unroll
        for (int kbl = 0; kbl < 4; ++kbl) {
            unsigned bfr[2][4][2];
#pragma unroll
            for (int term = 0; term < 2; ++term)
#pragma unroll
                for (int nt = 0; nt < 4; ++nt) {
                    int cb = wn * 32 + nt * 8 + g;
                    u64 v = bufu[4096 + ((size_t)(term * 4 + kbl) * 128 + cb) * 4 + tg];
                    bfr[term][nt][0] = (unsigned)v;
                    bfr[term][nt][1] = (unsigned)(v >> 32);
                }
            unsigned afr[2][2][4];
#pragma unroll
            for (int term = 0; term < 2; ++term)
#pragma unroll
                for (int mt = 0; mt < 2; ++mt) {
                    int ra = wm * 32 + mt * 16 + g;
                    u64 lo = bufu[((size_t)(term * 4 + kbl) * 128 + ra) * 4 + tg];
                    u64 hi = bufu[((size_t)(term * 4 + kbl) * 128 + ra + 8) * 4 + tg];
                    afr[term][mt][0] = (unsigned)lo;
                    afr[term][mt][1] = (unsigned)hi;
                    afr[term][mt][2] = (unsigned)(lo >> 32);
                    afr[term][mt][3] = (unsigned)(hi >> 32);
                }
#pragma unroll
            for (int mt = 0; mt < 2; ++mt)
#pragma unroll
                for (int nt = 0; nt < 4; ++nt) {
                    MMA16816(acc[mt][nt], afr[0][mt], bfr[0][nt]);  // x1*W1
                    MMA16816(acc[mt][nt], afr[0][mt], bfr[1][nt]);  // x1*W2
                    MMA16816(acc[mt][nt], afr[1][mt], bfr[0][nt]);  // x2*W1
                }
        }
    }

#pragma unroll
    for (int mt = 0; mt < 2; ++mt)
#pragma unroll
        for (int nt = 0; nt < 4; ++nt) {
            const int r0 = m0g + wm * 32 + mt * 16 + g;
            const int r1 = r0 + 8;
            const int nc = n0 + wn * 32 + nt * 8 + 2 * tg;
            float2 bv = *reinterpret_cast<const float2*>(g_bias + nc);
            float2 o0 = make_float2(acc[mt][nt][0] + bv.x, acc[mt][nt][1] + bv.y);
            float2 o1 = make_float2(acc[mt][nt][2] + bv.x, acc[mt][nt][3] + bv.y);
            *reinterpret_cast<float2*>(&g_Gx[(size_t)r0 * NGATE + nc]) = o0;
            *reinterpret_cast<float2*>(&g_Gx[(size_t)r1 * NGATE + nc]) = o1;
        }
}

// ---------------- persistent recurrence: bf16-split-3 mma + bulk-async h staging ----------
// Same structure as R15 EXCEPT h chunk staging: tid0 issues cp.async.bulk (2 x 16 KB
// contiguous per chunk) completing on per-buffer mbarriers — removes ~2048 LDGSTS
// issue-slots per SMSP per step. Pipeline: wait mbar[c%3] -> bar -> issue c+2 -> compute c.
__global__ __launch_bounds__(NT, 1) void lstm_persist(float* __restrict__ yout) {
    extern __shared__ float4 smf[];
    float4* Ws_f4 = smf;            // 8192 f4 = 128 KB, [term][kb][c][tg]
    float4* hs_f4 = smf + 8192;     // 3 x 2048 f4 = 96 KB pipeline buffers
    u64*    mbar  = reinterpret_cast<u64*>(smf + 8192 + 3 * 2048);  // 3 mbarriers

    const int tid  = threadIdx.x;
    const int wid  = tid >> 5;
    const int lane = tid & 31;
    const int kg   = wid & 1;
    const int wq   = wid >> 1;
    const int wm   = wq >> 1;       // 0..3
    const int wn   = wq & 1;        // 0..1
    const int m0   = wm * 32;
    const int g    = lane >> 2;     // 0..7
    const int tg   = lane & 3;      // 0..3
    const int n0   = blockIdx.x * 32;

    // --- one-time: Wh split slice -> SMEM (linear copy, frag layout preserved) ---
    {
        const float4* src = g_Whf + (size_t)blockIdx.x * 8192;
#pragma unroll
        for (int it = 0; it < 16; ++it) Ws_f4[tid + it * NT] = __ldcg(&src[tid + it * NT]);
    }
    if (tid == 0) {
        mbar_init(&mbar[0], 1);
        mbar_init(&mbar[1], 1);
        mbar_init(&mbar[2], 1);
    }
    __syncthreads();

    const char* Wsb = reinterpret_cast<const char*>(Ws_f4);

    unsigned ph0 = 0, ph1 = 0, ph2 = 0;   // per-buffer mbarrier phase parity

    float cs[2][2][2];              // cell state per (mt, nt, row-half), kg0 even-tg threads
#pragma unroll
    for (int a = 0; a < 2; ++a)
#pragma unroll
        for (int b = 0; b < 2; ++b) { cs[a][b][0] = 0.f; cs[a][b][1] = 0.f; }

    for (int t = 0; t < S_LEN; ++t) {
        const int pp_cur = t & 1;
        const int pp_nxt = (t + 1) & 1;
        const float4* hsrc = g_hf + (size_t)(pp_cur * 2) * 16384;  // [term][...]

        // Gx epilogue operands: issue now, consumed ~a whole chunk-loop later
        float2 gxa[2][2], gxb[2][2];
        if (kg == 0) {
#pragma unroll
            for (int mt = 0; mt < 2; ++mt)
#pragma unroll
                for (int nt = 0; nt < 2; ++nt) {
                    const int r0 = m0 + mt * 16 + g;
                    const int ne = wn * 16 + nt * 8 + 2 * tg;
                    gxa[mt][nt] = __ldcg(reinterpret_cast<const float2*>(
                        &g_Gx[((size_t)r0 * S_LEN + t) * NGATE + n0 + ne]));
                    gxb[mt][nt] = __ldcg(reinterpret_cast<const float2*>(
                        &g_Gx[((size_t)(r0 + 8) * S_LEN + t) * NGATE + n0 + ne]));
                }
        }

        // pipeline prologue: chunks 0 and 1 in flight (tid0, bulk copies)
        if (tid == 0) {
#pragma unroll
            for (int c0 = 0; c0 < 2; ++c0) {
                mbar_expect_tx(&mbar[c0], 32768u);
                cpbulk(hs_f4 + c0 * 2048,
                       hsrc + (size_t)c0 * 1024, 16384u, &mbar[c0]);
                cpbulk(hs_f4 + c0 * 2048 + 1024,
                       hsrc + 16384 + (size_t)c0 * 1024, 16384u, &mbar[c0]);
            }
        }

        float acc[2][2][4];
#pragma unroll
        for (int a = 0; a < 2; ++a)
#pragma unroll
            for (int b = 0; b < 2; ++b)
#pragma unroll
                for (int q = 0; q < 4; ++q) acc[a][b][q] = 0.f;

        for (int c = 0; c < 16; ++c) {
            // wait chunk c data (buffer c%3), flip that buffer's parity
            const int b3 = c % 3;
            if (b3 == 0)      { mbar_wait(&mbar[0], ph0); ph0 ^= 1u; }
            else if (b3 == 1) { mbar_wait(&mbar[1], ph1); ph1 ^= 1u; }
            else              { mbar_wait(&mbar[2], ph2); ph2 ^= 1u; }
            __syncthreads();    // all threads past compute of chunk c-1 (buffer (c+2)%3 free)

            if (tid == 0 && c + 2 < 16) {   // issue chunk c+2
                const int nb3 = (c + 2) % 3;
                mbar_expect_tx(&mbar[nb3], 32768u);
                cpbulk(hs_f4 + nb3 * 2048,
                       hsrc + (size_t)(c + 2) * 1024, 16384u, &mbar[nb3]);
                cpbulk(hs_f4 + nb3 * 2048 + 1024,
                       hsrc + 16384 + (size_t)(c + 2) * 1024, 16384u, &mbar[nb3]);
            }

            const char* hsb = reinterpret_cast<const char*>(hs_f4 + b3 * 2048);
#pragma unroll
            for (int kk = 0; kk < 2; ++kk) {
                const int kbl = kg * 2 + kk;        // 0..3 within chunk
                const int kb  = c * 4 + kbl;        // global k-block

                // B fragments: [term][nt][2]
                unsigned bfr[2][2][2];
#pragma unroll
                for (int term = 0; term < 2; ++term)
#pragma unroll
                    for (int nt = 0; nt < 2; ++nt) {
                        u64 v = *reinterpret_cast<const u64*>(
                            Wsb + ((((size_t)(term * 64 + kb) * 32) +
                                    (wn * 16 + nt * 8 + g)) * 4 + tg) * 8);
                        bfr[term][nt][0] = (unsigned)v;
                        bfr[term][nt][1] = (unsigned)(v >> 32);
                    }

                // A fragments: [term][mt][4] = {lo.x, hi.x, lo.y, hi.y}
                unsigned afr[2][2][4];
#pragma unroll
                for (int term = 0; term < 2; ++term)
#pragma unroll
                    for (int mt = 0; mt < 2; ++mt) {
                        const char* pA = hsb + (size_t)term * 16384 +
                            (((size_t)(kbl * 128 + m0 + mt * 16 + g)) * 4 + tg) * 8;
                        u64 lo = *reinterpret_cast<const u64*>(pA);
                        u64 hi = *reinterpret_cast<const u64*>(pA + 256);  // +8 rows
                        afr[term][mt][0] = (unsigned)lo;
                        afr[term][mt][1] = (unsigned)hi;
                        afr[term][mt][2] = (unsigned)(lo >> 32);
                        afr[term][mt][3] = (unsigned)(hi >> 32);
                    }

#pragma unroll
                for (int mt = 0; mt < 2; ++mt)
#pragma unroll
                    for (int nt = 0; nt < 2; ++nt) {
                        MMA16816(acc[mt][nt], afr[0][mt], bfr[0][nt]);  // h1*W1
                        MMA16816(acc[mt][nt], afr[0][mt], bfr[1][nt]);  // h1*W2
                        MMA16816(acc[mt][nt], afr[1][mt], bfr[0][nt]);  // h2*W1
                    }
            }
        }

        // all compute done reading hs buffers before reduce reuses buf 0
        __syncthreads();

        // --- cross-kg reduce via SMEM (kg1 -> kg0) ---
        float4* red = hs_f4;
        if (kg == 1) {
#pragma unroll
            for (int q = 0; q < 4; ++q) {
                int mt = q >> 1, nt = q & 1;
                red[q * 256 + wq * 32 + lane] =
                    make_float4(acc[mt][nt][0], acc[mt][nt][1], acc[mt][nt][2], acc[mt][nt][3]);
            }
        }
        __syncthreads();
        if (kg == 0) {
#pragma unroll
            for (int q = 0; q < 4; ++q) {
                int mt = q >> 1, nt = q & 1;
                float4 r = red[q * 256 + wq * 32 + lane];
                acc[mt][nt][0] += r.x; acc[mt][nt][1] += r.y;
                acc[mt][nt][2] += r.z; acc[mt][nt][3] += r.w;
            }

            // --- LSTM cell epilogue ---
#pragma unroll
            for (int mt = 0; mt < 2; ++mt)
#pragma unroll
                for (int nt = 0; nt < 2; ++nt) {
                    const int r0 = m0 + mt * 16 + g;
                    const int r1 = r0 + 8;
                    const int ne = wn * 16 + nt * 8 + 2 * tg;
                    float p00 = acc[mt][nt][0] + gxa[mt][nt].x;
                    float p01 = acc[mt][nt][1] + gxa[mt][nt].y;
                    float p10 = acc[mt][nt][2] + gxb[mt][nt].x;
                    float p11 = acc[mt][nt][3] + gxb[mt][nt].y;
                    // exchange with partner lane (tg^1): it holds the other gate pair
                    u64 y0 = __shfl_xor_sync(0xffffffffu, pack2(p00, p01), 1);
                    u64 y1 = __shfl_xor_sync(0xffffffffu, pack2(p10, p11), 1);
                    if ((tg & 1) == 0) {
                        const int u = (n0 + ne) >> 2;   // hidden unit
                        float2 go0 = unpack2(y0);
                        float2 go1 = unpack2(y1);
                        // row r0
                        {
                            float fg = sigm_(p00), ig = sigm_(p01);
                            float gg = tanh_(go0.x), og = sigm_(go0.y);
                            cs[mt][nt][0] = cs[mt][nt][0] * fg + ig * gg;
                            float hv = tanh_(cs[mt][nt][0]) * og;
                            __nv_bfloat16 h1 = __float2bfloat16(hv);
                            __nv_bfloat16 h2 = __float2bfloat16(hv - __bfloat162float(h1));
                            int kb_ = u >> 4, tgh, phh; jj_to_tgp(u & 15, tgh, phh);
                            __nv_bfloat16* hb = reinterpret_cast<__nv_bfloat16*>(g_hf);
                            size_t u1 = (((size_t)(pp_nxt * 2 + 0) * 64 + kb_) * 128 + r0) * 4 + tgh;
                            size_t u2 = (((size_t)(pp_nxt * 2 + 1) * 64 + kb_) * 128 + r0) * 4 + tgh;
                            st_cg_b16(&hb[u1 * 4 + phh], h1);
                            st_cg_b16(&hb[u2 * 4 + phh], h2);
                            yout[((size_t)r0 * S_LEN + t) * HID + u] = hv;
                        }
                        // row r1
                        {
                            float fg = sigm_(p10), ig = sigm_(p11);
                            float gg = tanh_(go1.x), og = sigm_(go1.y);
                            cs[mt][nt][1] = cs[mt][nt][1] * fg + ig * gg;
                            float hv = tanh_(cs[mt][nt][1]) * og;
                            __nv_bfloat16 h1 = __float2bfloat16(hv);
                            __nv_bfloat16 h2 = __float2bfloat16(hv - __bfloat162float(h1));
                            int kb_ = u >> 4, tgh, phh; jj_to_tgp(u & 15, tgh, phh);
                            __nv_bfloat16* hb = reinterpret_cast<__nv_bfloat16*>(g_hf);
                            size_t u1 = (((size_t)(pp_nxt * 2 + 0) * 64 + kb_) * 128 + r1) * 4 + tgh;
                            size_t u2 = (((size_t)(pp_nxt * 2 + 1) * 64 + kb_) * 128 + r1) * 4 + tgh;
                            st_cg_b16(&hb[u1 * 4 + phh], h1);
                            st_cg_b16(&hb[u2 * 4 + phh], h2);
                            yout[((size_t)r1 * S_LEN + t) * HID + u] = hv;
                        }
                    }
                }
        }

        // --- grid barrier (release/acquire), proven in R10/R12/R14/R15 ---
        __syncthreads();   // epilogue stores ordered before tid0's release-arrive
        if (tid == 0) {
            unsigned old = atomAddRelease(&g_arrive, 1u);
            if (old == NB - 1) {
                asm volatile("st.global.relaxed.gpu.u32 [%0], %1;"
                             :: "l"(&g_arrive), "r"(0u) : "memory");
                atomAddRelease(&g_epoch, 1u);
            } else {
                unsigned target = (unsigned)t + 1u;
                while (ldAcquire(&g_epoch) < target) {}
            }
        }
        __syncthreads();   // propagate acquire to all threads
    }
}

// ---------------- launch ----------------
extern "C" void kernel_launch(void* const* d_in, const int* in_sizes, int n_in,
                              void* d_out, int out_size) {
    const float* x  = (const float*)d_in[0];
    const float* Wf = (const float*)d_in[1]; const float* bf = (const float*)d_in[2];
    const float* Wi = (const float*)d_in[3]; const float* bi = (const float*)d_in[4];
    const float* Wc = (const float*)d_in[5]; const float* bc = (const float*)d_in[6];
    const float* Wo = (const float*)d_in[7]; const float* bo = (const float*)d_in[8];
    float* out = (float*)d_out;

    init_state<<<(2 * 16384 + 255) / 256, 256>>>();
    repack<<<(NGATE * KDIM + 255) / 256, 256>>>(Wf, bf, Wi, bi, Wc, bc, Wo, bo);
    xsplit<<<(64 * 32768 * 4 + 255) / 256, 256>>>(x);

    // Precompute Gx = bias + x @ Wx^T via bf16 split-3 tensor cores
    const int pre_smem = 3 * 4096 * (int)sizeof(float4);   // 196608 B = 192 KB
    cudaFuncSetAttribute(gemm_pre_mma, cudaFuncAttributeMaxDynamicSharedMemorySize, pre_smem);
    gemm_pre_mma<<<dim3(NGATE / 128, (BATCH * S_LEN) / 128), 512, pre_smem>>>();

    // Persistent recurrence: bulk-async (UBLKCP) pipelined h staging
    const int smem_bytes = (8192 + 3 * 2048) * (int)sizeof(float4) + 64;  // 229440 B
    cudaFuncSetAttribute(lstm_persist, cudaFuncAttributeMaxDynamicSharedMemorySize, smem_bytes);
    lstm_persist<<<NB, NT, smem_bytes>>>(out);
}